// round 14
// baseline (speedup 1.0000x reference)
#include <cuda_runtime.h>

typedef unsigned long long ull;
typedef unsigned int u32;

#define NN 50000
#define DD 128
#define EE 1600000
#define TWO_N (2*NN)
#define SCAN_B 512
#define NSB ((TWO_N + SCAN_B - 1)/SCAN_B)
#define MT 128
#define NBLK_MM ((NN + MT - 1)/MT)   // 391
#define MMT 256

#define S_AHI 0
#define S_ALO 32768
#define S_B   65536
#define S_BIAS 98304
#define SMEM_MM 102400

#define WI_W1A 0
#define WI_W2A 1
#define WI_W1B 2
#define WI_W2B 3
#define WI_WO  4
#define WI_WF1 5
#define WI_WF2 6

// ---------------- scratch ----------------
__device__ int   g_cnt[TWO_N];
__device__ int   g_off[TWO_N + 1];
__device__ int   g_bsum[NSB];
__device__ int   g_col[2*EE];
__device__ float g_ua[NN*DD];
__device__ float g_ub[NN*DD];
__device__ uint4 g_wfrag[7*4096];

// ---------------- bf16 helpers ----------------
__device__ __forceinline__ u32 pkbf(float lo, float hi) {
    u32 r; asm("cvt.rn.bf16x2.f32 %0, %1, %2;" : "=r"(r) : "f"(hi), "f"(lo)); return r;
}
__device__ __forceinline__ float bf_lo(u32 p) { return __uint_as_float(p << 16); }
__device__ __forceinline__ float bf_hi(u32 p) { return __uint_as_float(p & 0xffff0000u); }

#define MMA4(d, a0, a1, a2, a3, b0, b1) \
    asm volatile("mma.sync.aligned.m16n8k16.row.col.f32.bf16.bf16.f32 " \
        "{%0,%1,%2,%3}, {%4,%5,%6,%7}, {%8,%9}, {%0,%1,%2,%3};" \
        : "+f"((d)[0]), "+f"((d)[1]), "+f"((d)[2]), "+f"((d)[3]) \
        : "r"(a0), "r"(a1), "r"(a2), "r"(a3), "r"(b0), "r"(b1))

// ---------------- one-time weight fragment prep ----------------
__global__ void prep_w(const float* __restrict__ W1a, const float* __restrict__ W2a,
                       const float* __restrict__ W1b, const float* __restrict__ W2b,
                       const float* __restrict__ Wo,  const float* __restrict__ Wf1,
                       const float* __restrict__ Wf2) {
    int idx = blockIdx.x*blockDim.x + threadIdx.x;
    if (idx >= 7*4096) return;
    const float* Ws[7] = {W1a, W2a, W1b, W2b, Wo, Wf1, Wf2};
    int w = idx >> 12;
    int rem = idx & 4095;
    int half = rem >> 11;
    int s = rem & 2047;
    int lane = s & 31, nt = (s >> 5) & 7, ks = s >> 8;
    int g = lane >> 2, c = lane & 3;
    const float* W = Ws[w];
    int n = half*64 + nt*8 + g;
    int k0 = ks*16 + 2*c;
    float w00 = W[(size_t)k0*128 + n];
    float w01 = W[(size_t)(k0+1)*128 + n];
    float w10 = W[(size_t)(k0+8)*128 + n];
    float w11 = W[(size_t)(k0+9)*128 + n];
    u32 bh0 = pkbf(w00, w01);
    u32 bh1 = pkbf(w10, w11);
    u32 bl0 = pkbf(w00 - bf_lo(bh0), w01 - bf_hi(bh0));
    u32 bl1 = pkbf(w10 - bf_lo(bh1), w11 - bf_hi(bh1));
    g_wfrag[idx] = make_uint4(bh0, bh1, bl0, bl1);
}

// ---------------- fragment staging ----------------
__device__ __forceinline__ void stage_A(u32* sAhi, u32* sAlo, const float* A, int row0) {
    for (int idx = threadIdx.x; idx < 128*64; idx += MMT) {
        int r = idx >> 6, j = idx & 63;
        int row = row0 + r;
        float v0 = 0.f, v1 = 0.f;
        if (row < NN) {
            float2 vv = *(const float2*)(A + (size_t)row*128 + 2*j);
            v0 = vv.x; v1 = vv.y;
        }
        u32 hp = pkbf(v0, v1);
        u32 lp = pkbf(v0 - bf_lo(hp), v1 - bf_hi(hp));
        int ks = j >> 3;
        int reg = ((r >> 3) & 1) | ((j & 4) ? 2 : 0);
        int ln  = (r & 7)*4 + (j & 3);
        int mt  = r >> 4;
        int o = ((ks*8 + mt)*32 + ln)*4 + reg;
        sAhi[o] = hp; sAlo[o] = lp;
    }
}

__device__ __forceinline__ void stage_W(u32* sB, const uint4* __restrict__ gw) {
    uint4* dst = (uint4*)sB;
    #pragma unroll
    for (int i = threadIdx.x; i < 2048; i += MMT) dst[i] = gw[i];
}

__device__ __forceinline__ void mma_half(const u32* sAhi, const u32* sAlo, const u32* sB,
                                         int wid, int lane, float acc[8][4]) {
    #pragma unroll
    for (int nt = 0; nt < 8; nt++)
        #pragma unroll
        for (int q = 0; q < 4; q++) acc[nt][q] = 0.f;
    #pragma unroll
    for (int ks = 0; ks < 8; ks++) {
        uint4 ah = *(const uint4*)(sAhi + ((ks*8 + wid)*32 + lane)*4);
        uint4 al = *(const uint4*)(sAlo + ((ks*8 + wid)*32 + lane)*4);
        #pragma unroll
        for (int nt = 0; nt < 8; nt++) {
            uint4 b = *(const uint4*)(sB + ((ks*8 + nt)*32 + lane)*4);
            MMA4(acc[nt], ah.x, ah.y, ah.z, ah.w, b.x, b.y);
            MMA4(acc[nt], al.x, al.y, al.z, al.w, b.x, b.y);
            MMA4(acc[nt], ah.x, ah.y, ah.z, ah.w, b.z, b.w);
        }
    }
}

__device__ __forceinline__ void layer(u32* sAhi, u32* sAlo, u32* sB,
                                      const uint4* __restrict__ gw,
                                      int wid, int lane,
                                      float acc0[8][4], float acc1[8][4]) {
    __syncthreads();
    stage_W(sB, gw);
    __syncthreads();
    mma_half(sAhi, sAlo, sB, wid, lane, acc0);
    __syncthreads();
    stage_W(sB, gw + 2048);
    __syncthreads();
    mma_half(sAhi, sAlo, sB, wid, lane, acc1);
}

__device__ __forceinline__ void write_H(u32* sAhi, u32* sAlo,
                                        float acc0[8][4], float acc1[8][4],
                                        const float* bias, int wid, int lane) {
    int g = lane >> 2, c = lane & 3;
    #pragma unroll
    for (int half = 0; half < 2; half++) {
        float (*acc)[4] = half ? acc1 : acc0;
        #pragma unroll
        for (int nt = 0; nt < 8; nt++) {
            int col = half*64 + nt*8 + 2*c;
            float b0 = bias[col], b1 = bias[col+1];
            int j = col >> 1;
            int ks = j >> 3;
            int ln = g*4 + (j & 3);
            int base = ((ks*8 + wid)*32 + ln)*4 + ((j & 4) ? 2 : 0);
            #pragma unroll
            for (int pr = 0; pr < 2; pr++) {
                float v0 = fmaxf(acc[nt][pr*2]   + b0, 0.f);
                float v1 = fmaxf(acc[nt][pr*2+1] + b1, 0.f);
                u32 hp = pkbf(v0, v1);
                u32 lp = pkbf(v0 - bf_lo(hp), v1 - bf_hi(hp));
                sAhi[base + pr] = hp;
                sAlo[base + pr] = lp;
            }
        }
    }
}

// ================= fc_x =================
__global__ __launch_bounds__(MMT, 2) void fc_x_mm(
    const float* __restrict__ X,
    const uint4* __restrict__ gwf,
    const float* __restrict__ B1, const float* __restrict__ B2,
    float* __restrict__ OUT)
{
    extern __shared__ char smc[];
    u32* sAhi = (u32*)(smc + S_AHI);
    u32* sAlo = (u32*)(smc + S_ALO);
    u32* sB   = (u32*)(smc + S_B);
    float* sb1 = (float*)(smc + S_BIAS);
    float* sb2 = (float*)(smc + S_BIAS + 512);

    const int tid = threadIdx.x;
    const int wid = tid >> 5, lane = tid & 31;
    const int row0 = blockIdx.x * MT;
    if (tid < 128) { sb1[tid] = B1[tid]; sb2[tid] = B2[tid]; }
    stage_A(sAhi, sAlo, X, row0);

    float acc0[8][4], acc1[8][4];
    layer(sAhi, sAlo, sB, gwf + WI_WF1*4096, wid, lane, acc0, acc1);
    write_H(sAhi, sAlo, acc0, acc1, sb1, wid, lane);
    layer(sAhi, sAlo, sB, gwf + WI_WF2*4096, wid, lane, acc0, acc1);

    int g = lane >> 2, c = lane & 3;
    int r0 = row0 + wid*16 + g;
    #pragma unroll
    for (int half = 0; half < 2; half++) {
        float (*acc)[4] = half ? acc1 : acc0;
        #pragma unroll
        for (int nt = 0; nt < 8; nt++) {
            int col = half*64 + nt*8 + 2*c;
            float b0 = sb2[col], b1 = sb2[col+1];
            #pragma unroll
            for (int pr = 0; pr < 2; pr++) {
                int row = r0 + pr*8;
                if (row < NN) {
                    float2 xv = *(const float2*)(X + (size_t)row*128 + col);
                    float2 o;
                    o.x = xv.x + acc[nt][pr*2]   + b0;
                    o.y = xv.y + acc[nt][pr*2+1] + b1;
                    *(float2*)(OUT + (size_t)row*128 + col) = o;
                }
            }
        }
    }
}

// ================= gin_a: partial = t + mlp_a(ua) + b2a -> g_ua =================
__global__ __launch_bounds__(MMT, 2) void gin_a_mm(
    float* __restrict__ ua, const float* __restrict__ t,
    const uint4* __restrict__ gwf,
    const float* __restrict__ b1a, const float* __restrict__ b2a)
{
    extern __shared__ char smc[];
    u32* sAhi = (u32*)(smc + S_AHI);
    u32* sAlo = (u32*)(smc + S_ALO);
    u32* sB   = (u32*)(smc + S_B);
    float* s_b1a = (float*)(smc + S_BIAS);
    float* s_b2a = (float*)(smc + S_BIAS + 512);

    const int tid = threadIdx.x;
    const int wid = tid >> 5, lane = tid & 31;
    const int g = lane >> 2, c = lane & 3;
    const int row0 = blockIdx.x * MT;
    const int r0 = row0 + wid*16 + g;

    if (tid < 128) { s_b1a[tid] = b1a[tid]; s_b2a[tid] = b2a[tid]; }
    stage_A(sAhi, sAlo, ua, row0);

    float acc0[8][4], acc1[8][4];
    layer(sAhi, sAlo, sB, gwf + WI_W1A*4096, wid, lane, acc0, acc1);
    write_H(sAhi, sAlo, acc0, acc1, s_b1a, wid, lane);
    layer(sAhi, sAlo, sB, gwf + WI_W2A*4096, wid, lane, acc0, acc1);

    #pragma unroll
    for (int half = 0; half < 2; half++) {
        float (*acc)[4] = half ? acc1 : acc0;
        #pragma unroll
        for (int nt = 0; nt < 8; nt++) {
            int col = half*64 + nt*8 + 2*c;
            float b0 = s_b2a[col], b1 = s_b2a[col+1];
            #pragma unroll
            for (int pr = 0; pr < 2; pr++) {
                int row = r0 + pr*8;
                if (row < NN) {
                    float2 tv = *(const float2*)(t + (size_t)row*128 + col);
                    float2 o;
                    o.x = tv.x + acc[nt][pr*2]   + b0;
                    o.y = tv.y + acc[nt][pr*2+1] + b1;
                    *(float2*)(ua + (size_t)row*128 + col) = o;
                }
            }
        }
    }
}

// ================= fused_rest: gin_b + t2 + out-Linear + LN =================
__global__ __launch_bounds__(MMT, 2) void fused_rest_mm(
    const float* __restrict__ partial, const float* __restrict__ ub,
    const uint4* __restrict__ gwf,
    const float* __restrict__ b1b, const float* __restrict__ b2b,
    const float* __restrict__ bo,
    const float* __restrict__ lng, const float* __restrict__ lnb,
    float* __restrict__ OUT)
{
    extern __shared__ char smc[];
    u32* sAhi = (u32*)(smc + S_AHI);
    u32* sAlo = (u32*)(smc + S_ALO);
    u32* sB   = (u32*)(smc + S_B);
    float* s_b1b = (float*)(smc + S_BIAS);
    float* s_b2b = (float*)(smc + S_BIAS + 512);
    float* s_bo  = (float*)(smc + S_BIAS + 1024);
    float* s_g   = (float*)(smc + S_BIAS + 1536);
    float* s_be  = (float*)(smc + S_BIAS + 2048);

    const int tid = threadIdx.x;
    const int wid = tid >> 5, lane = tid & 31;
    const int g = lane >> 2, c = lane & 3;
    const int row0 = blockIdx.x * MT;
    const int r0 = row0 + wid*16 + g;

    if (tid < 128) {
        s_b1b[tid] = b1b[tid]; s_b2b[tid] = b2b[tid];
        s_bo[tid]  = bo[tid];  s_g[tid]   = lng[tid]; s_be[tid] = lnb[tid];
    }
    stage_A(sAhi, sAlo, ub, row0);

    float acc0[8][4], acc1[8][4];
    layer(sAhi, sAlo, sB, gwf + WI_W1B*4096, wid, lane, acc0, acc1);
    write_H(sAhi, sAlo, acc0, acc1, s_b1b, wid, lane);
    layer(sAhi, sAlo, sB, gwf + WI_W2B*4096, wid, lane, acc0, acc1);

    // t2 = relu(partial + gb + b2b) -> A frags (input of Wo layer)
    #pragma unroll
    for (int half = 0; half < 2; half++) {
        float (*acc)[4] = half ? acc1 : acc0;
        #pragma unroll
        for (int nt = 0; nt < 8; nt++) {
            int col = half*64 + nt*8 + 2*c;
            float b0 = s_b2b[col], b1 = s_b2b[col+1];
            int j = col >> 1;
            int ks = j >> 3;
            int ln = g*4 + (j & 3);
            int base = ((ks*8 + wid)*32 + ln)*4 + ((j & 4) ? 2 : 0);
            #pragma unroll
            for (int pr = 0; pr < 2; pr++) {
                int row = r0 + pr*8;
                float p0 = 0.f, p1 = 0.f;
                if (row < NN) {
                    float2 pv = *(const float2*)(partial + (size_t)row*128 + col);
                    p0 = pv.x; p1 = pv.y;
                }
                float v0 = fmaxf(p0 + acc[nt][pr*2]   + b0, 0.f);
                float v1 = fmaxf(p1 + acc[nt][pr*2+1] + b1, 0.f);
                u32 hp = pkbf(v0, v1);
                u32 lp = pkbf(v0 - bf_lo(hp), v1 - bf_hi(hp));
                sAhi[base + pr] = hp;
                sAlo[base + pr] = lp;
            }
        }
    }

    layer(sAhi, sAlo, sB, gwf + WI_WO*4096, wid, lane, acc0, acc1);

    float s0 = 0.f, q0 = 0.f, s1 = 0.f, q1 = 0.f;
    #pragma unroll
    for (int half = 0; half < 2; half++) {
        float (*acc)[4] = half ? acc1 : acc0;
        #pragma unroll
        for (int nt = 0; nt < 8; nt++) {
            int col = half*64 + nt*8 + 2*c;
            float b0 = s_bo[col], b1 = s_bo[col+1];
            float z00 = fmaxf(acc[nt][0] + b0, 0.f);
            float z01 = fmaxf(acc[nt][1] + b1, 0.f);
            float z10 = fmaxf(acc[nt][2] + b0, 0.f);
            float z11 = fmaxf(acc[nt][3] + b1, 0.f);
            s0 += z00 + z01; q0 += z00*z00 + z01*z01;
            s1 += z10 + z11; q1 += z10*z10 + z11*z11;
        }
    }
    #pragma unroll
    for (int d = 1; d <= 2; d <<= 1) {
        s0 += __shfl_xor_sync(0xffffffffu, s0, d);
        q0 += __shfl_xor_sync(0xffffffffu, q0, d);
        s1 += __shfl_xor_sync(0xffffffffu, s1, d);
        q1 += __shfl_xor_sync(0xffffffffu, q1, d);
    }
    float m0 = s0*(1.f/128.f), m1 = s1*(1.f/128.f);
    float rs0 = rsqrtf(q0*(1.f/128.f) - m0*m0 + 1e-5f);
    float rs1 = rsqrtf(q1*(1.f/128.f) - m1*m1 + 1e-5f);

    #pragma unroll
    for (int half = 0; half < 2; half++) {
        float (*acc)[4] = half ? acc1 : acc0;
        #pragma unroll
        for (int nt = 0; nt < 8; nt++) {
            int col = half*64 + nt*8 + 2*c;
            float b0 = s_bo[col], b1 = s_bo[col+1];
            float g0 = s_g[col], g1 = s_g[col+1];
            float e0 = s_be[col], e1 = s_be[col+1];
            int j = col >> 1;
            int ks = j >> 3;
            int ln = g*4 + (j & 3);
            int base = ((ks*8 + wid)*32 + ln)*4 + ((j & 4) ? 2 : 0);
            #pragma unroll
            for (int pr = 0; pr < 2; pr++) {
                int row = r0 + pr*8;
                if (row < NN) {
                    float mm = pr ? m1 : m0;
                    float rr = pr ? rs1 : rs0;
                    u32 hp = sAhi[base + pr], lp = sAlo[base + pr];
                    float t20 = bf_lo(hp) + bf_lo(lp);
                    float t21 = bf_hi(hp) + bf_hi(lp);
                    float z0 = fmaxf(acc[nt][pr*2]   + b0, 0.f);
                    float z1 = fmaxf(acc[nt][pr*2+1] + b1, 0.f);
                    float2 o;
                    o.x = t20 + (z0 - mm)*rr*g0 + e0;
                    o.y = t21 + (z1 - mm)*rr*g1 + e1;
                    *(float2*)(OUT + (size_t)row*128 + col) = o;
                }
            }
        }
    }
}

// ---------------- CSR construction ----------------
__global__ void zero_cnt_kernel() {
    int i = blockIdx.x*blockDim.x + threadIdx.x;
    if (i < TWO_N) g_cnt[i] = 0;
}

__global__ void hist_kernel(const int* __restrict__ et, const int* __restrict__ ex) {
    int i = blockIdx.x*blockDim.x + threadIdx.x;
    if (i < EE) {
        atomicAdd(&g_cnt[et[EE + i]], 1);
        atomicAdd(&g_cnt[NN + ex[EE + i]], 1);
    }
}

__global__ void scan1_kernel() {
    __shared__ int s[SCAN_B];
    int i = blockIdx.x*SCAN_B + threadIdx.x;
    int v = (i < TWO_N) ? g_cnt[i] : 0;
    s[threadIdx.x] = v;
    __syncthreads();
    #pragma unroll
    for (int d = 1; d < SCAN_B; d <<= 1) {
        int tv = (threadIdx.x >= d) ? s[threadIdx.x - d] : 0;
        __syncthreads();
        s[threadIdx.x] += tv;
        __syncthreads();
    }
    if (i < TWO_N) g_off[i + 1] = s[threadIdx.x];
    if (threadIdx.x == SCAN_B - 1) g_bsum[blockIdx.x] = s[SCAN_B - 1];
}

__global__ void scan2_kernel() {
    __shared__ int s[256];
    int v = (threadIdx.x < NSB) ? g_bsum[threadIdx.x] : 0;
    s[threadIdx.x] = v;
    __syncthreads();
    #pragma unroll
    for (int d = 1; d < 256; d <<= 1) {
        int tv = (threadIdx.x >= d) ? s[threadIdx.x - d] : 0;
        __syncthreads();
        s[threadIdx.x] += tv;
        __syncthreads();
    }
    if (threadIdx.x < NSB) g_bsum[threadIdx.x] = s[threadIdx.x] - v;
}

__global__ void scan3_kernel() {
    int i = blockIdx.x*blockDim.x + threadIdx.x;
    if (i == 0) { g_off[0] = 0; g_cnt[0] = 0; }
    else if (i <= TWO_N) {
        int v = g_off[i] + g_bsum[(i - 1) / SCAN_B];
        g_off[i] = v;
        if (i < TWO_N) g_cnt[i] = v;
    }
}

// fill set A (e_t) only
__global__ void fillA_kernel(const int* __restrict__ et) {
    int i = blockIdx.x*blockDim.x + threadIdx.x;
    if (i < EE) {
        int p = atomicAdd(&g_cnt[et[EE + i]], 1);
        g_col[p] = et[i];
    }
}

// fill set B (e_xct) only
__global__ void fillB_kernel(const int* __restrict__ ex) {
    int i = blockIdx.x*blockDim.x + threadIdx.x;
    if (i < EE) {
        int q = atomicAdd(&g_cnt[NN + ex[EE + i]], 1);
        g_col[q] = ex[i];
    }
}

// agg set A: ua = t + sum t[src]
__global__ void aggA_kernel(const float* __restrict__ t, float* __restrict__ ua) {
    int warp = (blockIdx.x*blockDim.x + threadIdx.x) >> 5;
    int lane = threadIdx.x & 31;
    if (warp >= NN) return;
    const float4* t4 = (const float4*)t;
    float4 aA = t4[warp*32 + lane];
    int e = g_off[warp], eE = g_off[warp + 1];
    for (; e + 3 < eE; e += 4) {
        int s0 = g_col[e], s1 = g_col[e+1], s2 = g_col[e+2], s3 = g_col[e+3];
        float4 v0 = t4[s0*32 + lane];
        float4 v1 = t4[s1*32 + lane];
        float4 v2 = t4[s2*32 + lane];
        float4 v3 = t4[s3*32 + lane];
        aA.x += v0.x + v1.x + v2.x + v3.x;
        aA.y += v0.y + v1.y + v2.y + v3.y;
        aA.z += v0.z + v1.z + v2.z + v3.z;
        aA.w += v0.w + v1.w + v2.w + v3.w;
    }
    for (; e < eE; e++) {
        int s0 = g_col[e];
        float4 v0 = t4[s0*32 + lane];
        aA.x += v0.x; aA.y += v0.y; aA.z += v0.z; aA.w += v0.w;
    }
    ((float4*)ua)[warp*32 + lane] = aA;
}

// agg set B: ub = t + sum x[src]
__global__ void aggB_kernel(const float* __restrict__ x, const float* __restrict__ t,
                            float* __restrict__ ub) {
    int warp = (blockIdx.x*blockDim.x + threadIdx.x) >> 5;
    int lane = threadIdx.x & 31;
    if (warp >= NN) return;
    const float4* t4 = (const float4*)t;
    const float4* x4 = (const float4*)x;
    float4 aB = t4[warp*32 + lane];
    int e = g_off[NN + warp], eE = g_off[NN + warp + 1];
    for (; e + 3 < eE; e += 4) {
        int s0 = g_col[e], s1 = g_col[e+1], s2 = g_col[e+2], s3 = g_col[e+3];
        float4 v0 = x4[s0*32 + lane];
        float4 v1 = x4[s1*32 + lane];
        float4 v2 = x4[s2*32 + lane];
        float4 v3 = x4[s3*32 + lane];
        aB.x += v0.x + v1.x + v2.x + v3.x;
        aB.y += v0.y + v1.y + v2.y + v3.y;
        aB.z += v0.z + v1.z + v2.z + v3.z;
        aB.w += v0.w + v1.w + v2.w + v3.w;
    }
    for (; e < eE; e++) {
        int s0 = g_col[e];
        float4 v0 = x4[s0*32 + lane];
        aB.x += v0.x; aB.y += v0.y; aB.z += v0.z; aB.w += v0.w;
    }
    ((float4*)ub)[warp*32 + lane] = aB;
}

// ---------------- launcher ----------------
extern "C" void kernel_launch(void* const* d_in, const int* in_sizes, int n_in,
                              void* d_out, int out_size) {
    const float* x   = (const float*)d_in[0];
    const float* t   = (const float*)d_in[1];
    const int*   et  = (const int*)d_in[2];
    const int*   ex  = (const int*)d_in[3];
    const float* W1a = (const float*)d_in[4];
    const float* b1a = (const float*)d_in[5];
    const float* W2a = (const float*)d_in[6];
    const float* b2a = (const float*)d_in[7];
    const float* W1b = (const float*)d_in[8];
    const float* b1b = (const float*)d_in[9];
    const float* W2b = (const float*)d_in[10];
    const float* b2b = (const float*)d_in[11];
    const float* Wo  = (const float*)d_in[12];
    const float* bo  = (const float*)d_in[13];
    const float* lng = (const float*)d_in[14];
    const float* lnb = (const float*)d_in[15];
    const float* Wf1 = (const float*)d_in[16];
    const float* bf1 = (const float*)d_in[17];
    const float* Wf2 = (const float*)d_in[18];
    const float* bf2 = (const float*)d_in[19];
    float* out = (float*)d_out;

    float *pua, *pub;
    uint4* pwf;
    cudaGetSymbolAddress((void**)&pua, g_ua);
    cudaGetSymbolAddress((void**)&pub, g_ub);
    cudaGetSymbolAddress((void**)&pwf, g_wfrag);

    cudaFuncSetAttribute(fc_x_mm,       cudaFuncAttributeMaxDynamicSharedMemorySize, SMEM_MM);
    cudaFuncSetAttribute(gin_a_mm,      cudaFuncAttributeMaxDynamicSharedMemorySize, SMEM_MM);
    cudaFuncSetAttribute(fused_rest_mm, cudaFuncAttributeMaxDynamicSharedMemorySize, SMEM_MM);

    cudaStream_t side;
    cudaStreamCreateWithFlags(&side, cudaStreamNonBlocking);
    cudaEvent_t eFork, eA, eG;
    cudaEventCreateWithFlags(&eFork, cudaEventDisableTiming);
    cudaEventCreateWithFlags(&eA, cudaEventDisableTiming);
    cudaEventCreateWithFlags(&eG, cudaEventDisableTiming);

    cudaEventRecord(eFork, 0);
    cudaStreamWaitEvent(side, eFork, 0);

    // side: weight prep -> fc_x -> (after aggA) gin_a
    prep_w<<<(7*4096 + 255)/256, 256, 0, side>>>(W1a, W2a, W1b, W2b, Wo, Wf1, Wf2);
    fc_x_mm<<<NBLK_MM, MMT, SMEM_MM, side>>>(x, pwf, bf1, bf2, out);

    // main: CSR build, set A first
    zero_cnt_kernel<<<(TWO_N + 1023)/1024, 1024>>>();
    hist_kernel<<<(EE + 255)/256, 256>>>(et, ex);
    scan1_kernel<<<NSB, SCAN_B>>>();
    scan2_kernel<<<1, 256>>>();
    scan3_kernel<<<(TWO_N + 1 + 255)/256, 256>>>();
    fillA_kernel<<<(EE + 255)/256, 256>>>(et);
    aggA_kernel<<<(NN + 7)/8, 256>>>(t, pua);
    cudaEventRecord(eA, 0);

    // side: gin_a overlaps main's fillB+aggB
    cudaStreamWaitEvent(side, eA, 0);
    gin_a_mm<<<NBLK_MM, MMT, SMEM_MM, side>>>(pua, t, pwf, b1a, b2a);
    cudaEventRecord(eG, side);

    // main: set B
    fillB_kernel<<<(EE + 255)/256, 256>>>(ex);
    aggB_kernel<<<(NN + 7)/8, 256>>>(x, t, pub);

    // join: fused_rest needs gin_a partial + ub
    cudaStreamWaitEvent(0, eG, 0);
    fused_rest_mm<<<NBLK_MM, MMT, SMEM_MM>>>(pua, pub, pwf,
        b1b, b2b, bo, lng, lnb, out + (size_t)NN*DD);

    cudaEventDestroy(eFork);
    cudaEventDestroy(eA);
    cudaEventDestroy(eG);
    cudaStreamDestroy(side);
}

// round 15
// speedup vs baseline: 1.0545x; 1.0545x over previous
#include <cuda_runtime.h>
#include <cuda_fp16.h>

typedef unsigned long long ull;
typedef unsigned int u32;

#define NN 50000
#define DD 128
#define EE 1600000
#define TWO_N (2*NN)
#define SCAN_B 512
#define NSB ((TWO_N + SCAN_B - 1)/SCAN_B)
#define MT 128
#define NBLK_MM ((NN + MT - 1)/MT)   // 391
#define MMT 256

#define S_AHI 0
#define S_ALO 32768
#define S_B   65536
#define S_BIAS 98304
#define SMEM_MM 102400

#define WI_W1A 0
#define WI_W2A 1
#define WI_W1B 2
#define WI_W2B 3
#define WI_WO  4
#define WI_WF1 5
#define WI_WF2 6

// ---------------- scratch ----------------
__device__ int   g_cnt[TWO_N];
__device__ int   g_off[TWO_N + 1];
__device__ int   g_bsum[NSB];
__device__ int   g_col[2*EE];
__device__ float g_ua[NN*DD];
__device__ float g_ub[NN*DD];
__device__ uint4 g_wfrag[7*4096];
__device__ u32   g_t16[NN*64];   // t as half2 pairs (row = 64 u32 = 256B)
__device__ u32   g_x16[NN*64];   // x as half2 pairs

// ---------------- bf16 helpers ----------------
__device__ __forceinline__ u32 pkbf(float lo, float hi) {
    u32 r; asm("cvt.rn.bf16x2.f32 %0, %1, %2;" : "=r"(r) : "f"(hi), "f"(lo)); return r;
}
__device__ __forceinline__ float bf_lo(u32 p) { return __uint_as_float(p << 16); }
__device__ __forceinline__ float bf_hi(u32 p) { return __uint_as_float(p & 0xffff0000u); }

#define MMA4(d, a0, a1, a2, a3, b0, b1) \
    asm volatile("mma.sync.aligned.m16n8k16.row.col.f32.bf16.bf16.f32 " \
        "{%0,%1,%2,%3}, {%4,%5,%6,%7}, {%8,%9}, {%0,%1,%2,%3};" \
        : "+f"((d)[0]), "+f"((d)[1]), "+f"((d)[2]), "+f"((d)[3]) \
        : "r"(a0), "r"(a1), "r"(a2), "r"(a3), "r"(b0), "r"(b1))

// ---------------- fp16 conversion (one-time) ----------------
__global__ void conv16_kernel(const float* __restrict__ t, const float* __restrict__ x) {
    int i = blockIdx.x*blockDim.x + threadIdx.x;
    if (i < NN*64) {
        float2 tv = ((const float2*)t)[i];
        float2 xv = ((const float2*)x)[i];
        __half2 th = __floats2half2_rn(tv.x, tv.y);
        __half2 xh = __floats2half2_rn(xv.x, xv.y);
        g_t16[i] = *(u32*)&th;
        g_x16[i] = *(u32*)&xh;
    }
}

// ---------------- one-time weight fragment prep ----------------
__global__ void prep_w(const float* __restrict__ W1a, const float* __restrict__ W2a,
                       const float* __restrict__ W1b, const float* __restrict__ W2b,
                       const float* __restrict__ Wo,  const float* __restrict__ Wf1,
                       const float* __restrict__ Wf2) {
    int idx = blockIdx.x*blockDim.x + threadIdx.x;
    if (idx >= 7*4096) return;
    const float* Ws[7] = {W1a, W2a, W1b, W2b, Wo, Wf1, Wf2};
    int w = idx >> 12;
    int rem = idx & 4095;
    int half = rem >> 11;
    int s = rem & 2047;
    int lane = s & 31, nt = (s >> 5) & 7, ks = s >> 8;
    int g = lane >> 2, c = lane & 3;
    const float* W = Ws[w];
    int n = half*64 + nt*8 + g;
    int k0 = ks*16 + 2*c;
    float w00 = W[(size_t)k0*128 + n];
    float w01 = W[(size_t)(k0+1)*128 + n];
    float w10 = W[(size_t)(k0+8)*128 + n];
    float w11 = W[(size_t)(k0+9)*128 + n];
    u32 bh0 = pkbf(w00, w01);
    u32 bh1 = pkbf(w10, w11);
    u32 bl0 = pkbf(w00 - bf_lo(bh0), w01 - bf_hi(bh0));
    u32 bl1 = pkbf(w10 - bf_lo(bh1), w11 - bf_hi(bh1));
    g_wfrag[idx] = make_uint4(bh0, bh1, bl0, bl1);
}

// ---------------- fragment staging ----------------
__device__ __forceinline__ void stage_A(u32* sAhi, u32* sAlo, const float* A, int row0) {
    for (int idx = threadIdx.x; idx < 128*64; idx += MMT) {
        int r = idx >> 6, j = idx & 63;
        int row = row0 + r;
        float v0 = 0.f, v1 = 0.f;
        if (row < NN) {
            float2 vv = *(const float2*)(A + (size_t)row*128 + 2*j);
            v0 = vv.x; v1 = vv.y;
        }
        u32 hp = pkbf(v0, v1);
        u32 lp = pkbf(v0 - bf_lo(hp), v1 - bf_hi(hp));
        int ks = j >> 3;
        int reg = ((r >> 3) & 1) | ((j & 4) ? 2 : 0);
        int ln  = (r & 7)*4 + (j & 3);
        int mt  = r >> 4;
        int o = ((ks*8 + mt)*32 + ln)*4 + reg;
        sAhi[o] = hp; sAlo[o] = lp;
    }
}

__device__ __forceinline__ void stage_W(u32* sB, const uint4* __restrict__ gw) {
    uint4* dst = (uint4*)sB;
    #pragma unroll
    for (int i = threadIdx.x; i < 2048; i += MMT) dst[i] = gw[i];
}

__device__ __forceinline__ void mma_half(const u32* sAhi, const u32* sAlo, const u32* sB,
                                         int wid, int lane, float acc[8][4]) {
    #pragma unroll
    for (int nt = 0; nt < 8; nt++)
        #pragma unroll
        for (int q = 0; q < 4; q++) acc[nt][q] = 0.f;
    #pragma unroll
    for (int ks = 0; ks < 8; ks++) {
        uint4 ah = *(const uint4*)(sAhi + ((ks*8 + wid)*32 + lane)*4);
        uint4 al = *(const uint4*)(sAlo + ((ks*8 + wid)*32 + lane)*4);
        #pragma unroll
        for (int nt = 0; nt < 8; nt++) {
            uint4 b = *(const uint4*)(sB + ((ks*8 + nt)*32 + lane)*4);
            MMA4(acc[nt], ah.x, ah.y, ah.z, ah.w, b.x, b.y);
            MMA4(acc[nt], al.x, al.y, al.z, al.w, b.x, b.y);
            MMA4(acc[nt], ah.x, ah.y, ah.z, ah.w, b.z, b.w);
        }
    }
}

__device__ __forceinline__ void layer(u32* sAhi, u32* sAlo, u32* sB,
                                      const uint4* __restrict__ gw,
                                      int wid, int lane,
                                      float acc0[8][4], float acc1[8][4]) {
    __syncthreads();
    stage_W(sB, gw);
    __syncthreads();
    mma_half(sAhi, sAlo, sB, wid, lane, acc0);
    __syncthreads();
    stage_W(sB, gw + 2048);
    __syncthreads();
    mma_half(sAhi, sAlo, sB, wid, lane, acc1);
}

__device__ __forceinline__ void write_H(u32* sAhi, u32* sAlo,
                                        float acc0[8][4], float acc1[8][4],
                                        const float* bias, int wid, int lane) {
    int g = lane >> 2, c = lane & 3;
    #pragma unroll
    for (int half = 0; half < 2; half++) {
        float (*acc)[4] = half ? acc1 : acc0;
        #pragma unroll
        for (int nt = 0; nt < 8; nt++) {
            int col = half*64 + nt*8 + 2*c;
            float b0 = bias[col], b1 = bias[col+1];
            int j = col >> 1;
            int ks = j >> 3;
            int ln = g*4 + (j & 3);
            int base = ((ks*8 + wid)*32 + ln)*4 + ((j & 4) ? 2 : 0);
            #pragma unroll
            for (int pr = 0; pr < 2; pr++) {
                float v0 = fmaxf(acc[nt][pr*2]   + b0, 0.f);
                float v1 = fmaxf(acc[nt][pr*2+1] + b1, 0.f);
                u32 hp = pkbf(v0, v1);
                u32 lp = pkbf(v0 - bf_lo(hp), v1 - bf_hi(hp));
                sAhi[base + pr] = hp;
                sAlo[base + pr] = lp;
            }
        }
    }
}

// ================= fc_x =================
__global__ __launch_bounds__(MMT, 2) void fc_x_mm(
    const float* __restrict__ X,
    const uint4* __restrict__ gwf,
    const float* __restrict__ B1, const float* __restrict__ B2,
    float* __restrict__ OUT)
{
    extern __shared__ char smc[];
    u32* sAhi = (u32*)(smc + S_AHI);
    u32* sAlo = (u32*)(smc + S_ALO);
    u32* sB   = (u32*)(smc + S_B);
    float* sb1 = (float*)(smc + S_BIAS);
    float* sb2 = (float*)(smc + S_BIAS + 512);

    const int tid = threadIdx.x;
    const int wid = tid >> 5, lane = tid & 31;
    const int row0 = blockIdx.x * MT;
    if (tid < 128) { sb1[tid] = B1[tid]; sb2[tid] = B2[tid]; }
    stage_A(sAhi, sAlo, X, row0);

    float acc0[8][4], acc1[8][4];
    layer(sAhi, sAlo, sB, gwf + WI_WF1*4096, wid, lane, acc0, acc1);
    write_H(sAhi, sAlo, acc0, acc1, sb1, wid, lane);
    layer(sAhi, sAlo, sB, gwf + WI_WF2*4096, wid, lane, acc0, acc1);

    int g = lane >> 2, c = lane & 3;
    int r0 = row0 + wid*16 + g;
    #pragma unroll
    for (int half = 0; half < 2; half++) {
        float (*acc)[4] = half ? acc1 : acc0;
        #pragma unroll
        for (int nt = 0; nt < 8; nt++) {
            int col = half*64 + nt*8 + 2*c;
            float b0 = sb2[col], b1 = sb2[col+1];
            #pragma unroll
            for (int pr = 0; pr < 2; pr++) {
                int row = r0 + pr*8;
                if (row < NN) {
                    float2 xv = *(const float2*)(X + (size_t)row*128 + col);
                    float2 o;
                    o.x = xv.x + acc[nt][pr*2]   + b0;
                    o.y = xv.y + acc[nt][pr*2+1] + b1;
                    *(float2*)(OUT + (size_t)row*128 + col) = o;
                }
            }
        }
    }
}

// ================= gin_a: partial = t + mlp_a(ua) + b2a -> g_ua =================
__global__ __launch_bounds__(MMT, 2) void gin_a_mm(
    float* __restrict__ ua, const float* __restrict__ t,
    const uint4* __restrict__ gwf,
    const float* __restrict__ b1a, const float* __restrict__ b2a)
{
    extern __shared__ char smc[];
    u32* sAhi = (u32*)(smc + S_AHI);
    u32* sAlo = (u32*)(smc + S_ALO);
    u32* sB   = (u32*)(smc + S_B);
    float* s_b1a = (float*)(smc + S_BIAS);
    float* s_b2a = (float*)(smc + S_BIAS + 512);

    const int tid = threadIdx.x;
    const int wid = tid >> 5, lane = tid & 31;
    const int g = lane >> 2, c = lane & 3;
    const int row0 = blockIdx.x * MT;
    const int r0 = row0 + wid*16 + g;

    if (tid < 128) { s_b1a[tid] = b1a[tid]; s_b2a[tid] = b2a[tid]; }
    stage_A(sAhi, sAlo, ua, row0);

    float acc0[8][4], acc1[8][4];
    layer(sAhi, sAlo, sB, gwf + WI_W1A*4096, wid, lane, acc0, acc1);
    write_H(sAhi, sAlo, acc0, acc1, s_b1a, wid, lane);
    layer(sAhi, sAlo, sB, gwf + WI_W2A*4096, wid, lane, acc0, acc1);

    #pragma unroll
    for (int half = 0; half < 2; half++) {
        float (*acc)[4] = half ? acc1 : acc0;
        #pragma unroll
        for (int nt = 0; nt < 8; nt++) {
            int col = half*64 + nt*8 + 2*c;
            float b0 = s_b2a[col], b1 = s_b2a[col+1];
            #pragma unroll
            for (int pr = 0; pr < 2; pr++) {
                int row = r0 + pr*8;
                if (row < NN) {
                    float2 tv = *(const float2*)(t + (size_t)row*128 + col);
                    float2 o;
                    o.x = tv.x + acc[nt][pr*2]   + b0;
                    o.y = tv.y + acc[nt][pr*2+1] + b1;
                    *(float2*)(ua + (size_t)row*128 + col) = o;
                }
            }
        }
    }
}

// ================= fused_rest: gin_b + t2 + out-Linear + LN =================
__global__ __launch_bounds__(MMT, 2) void fused_rest_mm(
    const float* __restrict__ partial, const float* __restrict__ ub,
    const uint4* __restrict__ gwf,
    const float* __restrict__ b1b, const float* __restrict__ b2b,
    const float* __restrict__ bo,
    const float* __restrict__ lng, const float* __restrict__ lnb,
    float* __restrict__ OUT)
{
    extern __shared__ char smc[];
    u32* sAhi = (u32*)(smc + S_AHI);
    u32* sAlo = (u32*)(smc + S_ALO);
    u32* sB   = (u32*)(smc + S_B);
    float* s_b1b = (float*)(smc + S_BIAS);
    float* s_b2b = (float*)(smc + S_BIAS + 512);
    float* s_bo  = (float*)(smc + S_BIAS + 1024);
    float* s_g   = (float*)(smc + S_BIAS + 1536);
    float* s_be  = (float*)(smc + S_BIAS + 2048);

    const int tid = threadIdx.x;
    const int wid = tid >> 5, lane = tid & 31;
    const int g = lane >> 2, c = lane & 3;
    const int row0 = blockIdx.x * MT;
    const int r0 = row0 + wid*16 + g;

    if (tid < 128) {
        s_b1b[tid] = b1b[tid]; s_b2b[tid] = b2b[tid];
        s_bo[tid]  = bo[tid];  s_g[tid]   = lng[tid]; s_be[tid] = lnb[tid];
    }
    stage_A(sAhi, sAlo, ub, row0);

    float acc0[8][4], acc1[8][4];
    layer(sAhi, sAlo, sB, gwf + WI_W1B*4096, wid, lane, acc0, acc1);
    write_H(sAhi, sAlo, acc0, acc1, s_b1b, wid, lane);
    layer(sAhi, sAlo, sB, gwf + WI_W2B*4096, wid, lane, acc0, acc1);

    // t2 = relu(partial + gb + b2b) -> A frags (input of Wo layer)
    #pragma unroll
    for (int half = 0; half < 2; half++) {
        float (*acc)[4] = half ? acc1 : acc0;
        #pragma unroll
        for (int nt = 0; nt < 8; nt++) {
            int col = half*64 + nt*8 + 2*c;
            float b0 = s_b2b[col], b1 = s_b2b[col+1];
            int j = col >> 1;
            int ks = j >> 3;
            int ln = g*4 + (j & 3);
            int base = ((ks*8 + wid)*32 + ln)*4 + ((j & 4) ? 2 : 0);
            #pragma unroll
            for (int pr = 0; pr < 2; pr++) {
                int row = r0 + pr*8;
                float p0 = 0.f, p1 = 0.f;
                if (row < NN) {
                    float2 pv = *(const float2*)(partial + (size_t)row*128 + col);
                    p0 = pv.x; p1 = pv.y;
                }
                float v0 = fmaxf(p0 + acc[nt][pr*2]   + b0, 0.f);
                float v1 = fmaxf(p1 + acc[nt][pr*2+1] + b1, 0.f);
                u32 hp = pkbf(v0, v1);
                u32 lp = pkbf(v0 - bf_lo(hp), v1 - bf_hi(hp));
                sAhi[base + pr] = hp;
                sAlo[base + pr] = lp;
            }
        }
    }

    layer(sAhi, sAlo, sB, gwf + WI_WO*4096, wid, lane, acc0, acc1);

    float s0 = 0.f, q0 = 0.f, s1 = 0.f, q1 = 0.f;
    #pragma unroll
    for (int half = 0; half < 2; half++) {
        float (*acc)[4] = half ? acc1 : acc0;
        #pragma unroll
        for (int nt = 0; nt < 8; nt++) {
            int col = half*64 + nt*8 + 2*c;
            float b0 = s_bo[col], b1 = s_bo[col+1];
            float z00 = fmaxf(acc[nt][0] + b0, 0.f);
            float z01 = fmaxf(acc[nt][1] + b1, 0.f);
            float z10 = fmaxf(acc[nt][2] + b0, 0.f);
            float z11 = fmaxf(acc[nt][3] + b1, 0.f);
            s0 += z00 + z01; q0 += z00*z00 + z01*z01;
            s1 += z10 + z11; q1 += z10*z10 + z11*z11;
        }
    }
    #pragma unroll
    for (int d = 1; d <= 2; d <<= 1) {
        s0 += __shfl_xor_sync(0xffffffffu, s0, d);
        q0 += __shfl_xor_sync(0xffffffffu, q0, d);
        s1 += __shfl_xor_sync(0xffffffffu, s1, d);
        q1 += __shfl_xor_sync(0xffffffffu, q1, d);
    }
    float m0 = s0*(1.f/128.f), m1 = s1*(1.f/128.f);
    float rs0 = rsqrtf(q0*(1.f/128.f) - m0*m0 + 1e-5f);
    float rs1 = rsqrtf(q1*(1.f/128.f) - m1*m1 + 1e-5f);

    #pragma unroll
    for (int half = 0; half < 2; half++) {
        float (*acc)[4] = half ? acc1 : acc0;
        #pragma unroll
        for (int nt = 0; nt < 8; nt++) {
            int col = half*64 + nt*8 + 2*c;
            float b0 = s_bo[col], b1 = s_bo[col+1];
            float g0 = s_g[col], g1 = s_g[col+1];
            float e0 = s_be[col], e1 = s_be[col+1];
            int j = col >> 1;
            int ks = j >> 3;
            int ln = g*4 + (j & 3);
            int base = ((ks*8 + wid)*32 + ln)*4 + ((j & 4) ? 2 : 0);
            #pragma unroll
            for (int pr = 0; pr < 2; pr++) {
                int row = r0 + pr*8;
                if (row < NN) {
                    float mm = pr ? m1 : m0;
                    float rr = pr ? rs1 : rs0;
                    u32 hp = sAhi[base + pr], lp = sAlo[base + pr];
                    float t20 = bf_lo(hp) + bf_lo(lp);
                    float t21 = bf_hi(hp) + bf_hi(lp);
                    float z0 = fmaxf(acc[nt][pr*2]   + b0, 0.f);
                    float z1 = fmaxf(acc[nt][pr*2+1] + b1, 0.f);
                    float2 o;
                    o.x = t20 + (z0 - mm)*rr*g0 + e0;
                    o.y = t21 + (z1 - mm)*rr*g1 + e1;
                    *(float2*)(OUT + (size_t)row*128 + col) = o;
                }
            }
        }
    }
}

// ---------------- CSR construction ----------------
__global__ void zero_cnt_kernel() {
    int i = blockIdx.x*blockDim.x + threadIdx.x;
    if (i < TWO_N) g_cnt[i] = 0;
}

__global__ void hist_kernel(const int* __restrict__ et, const int* __restrict__ ex) {
    int i = blockIdx.x*blockDim.x + threadIdx.x;
    if (i < EE) {
        atomicAdd(&g_cnt[et[EE + i]], 1);
        atomicAdd(&g_cnt[NN + ex[EE + i]], 1);
    }
}

__global__ void scan1_kernel() {
    __shared__ int s[SCAN_B];
    int i = blockIdx.x*SCAN_B + threadIdx.x;
    int v = (i < TWO_N) ? g_cnt[i] : 0;
    s[threadIdx.x] = v;
    __syncthreads();
    #pragma unroll
    for (int d = 1; d < SCAN_B; d <<= 1) {
        int tv = (threadIdx.x >= d) ? s[threadIdx.x - d] : 0;
        __syncthreads();
        s[threadIdx.x] += tv;
        __syncthreads();
    }
    if (i < TWO_N) g_off[i + 1] = s[threadIdx.x];
    if (threadIdx.x == SCAN_B - 1) g_bsum[blockIdx.x] = s[SCAN_B - 1];
}

__global__ void scan2_kernel() {
    __shared__ int s[256];
    int v = (threadIdx.x < NSB) ? g_bsum[threadIdx.x] : 0;
    s[threadIdx.x] = v;
    __syncthreads();
    #pragma unroll
    for (int d = 1; d < 256; d <<= 1) {
        int tv = (threadIdx.x >= d) ? s[threadIdx.x - d] : 0;
        __syncthreads();
        s[threadIdx.x] += tv;
        __syncthreads();
    }
    if (threadIdx.x < NSB) g_bsum[threadIdx.x] = s[threadIdx.x] - v;
}

__global__ void scan3_kernel() {
    int i = blockIdx.x*blockDim.x + threadIdx.x;
    if (i == 0) { g_off[0] = 0; g_cnt[0] = 0; }
    else if (i <= TWO_N) {
        int v = g_off[i] + g_bsum[(i - 1) / SCAN_B];
        g_off[i] = v;
        if (i < TWO_N) g_cnt[i] = v;
    }
}

__global__ void fillA_kernel(const int* __restrict__ et) {
    int i = blockIdx.x*blockDim.x + threadIdx.x;
    if (i < EE) {
        int p = atomicAdd(&g_cnt[et[EE + i]], 1);
        g_col[p] = et[i];
    }
}

__global__ void fillB_kernel(const int* __restrict__ ex) {
    int i = blockIdx.x*blockDim.x + threadIdx.x;
    if (i < EE) {
        int q = atomicAdd(&g_cnt[NN + ex[EE + i]], 1);
        g_col[q] = ex[i];
    }
}

// agg set A: ua = t + sum t16[src]  (fp16 gather, fp32 accumulate, exact t base)
__global__ void aggA_kernel(const float* __restrict__ t, float* __restrict__ ua) {
    int warp = (blockIdx.x*blockDim.x + threadIdx.x) >> 5;
    int lane = threadIdx.x & 31;
    if (warp >= NN) return;
    const float4* t4 = (const float4*)t;
    const uint2* s16 = (const uint2*)g_t16;    // row stride 32 uint2
    float4 aA = t4[warp*32 + lane];
    int e = g_off[warp], eE = g_off[warp + 1];
    for (; e + 3 < eE; e += 4) {
        int s0 = g_col[e], s1 = g_col[e+1], s2 = g_col[e+2], s3 = g_col[e+3];
        uint2 v0 = s16[s0*32 + lane];
        uint2 v1 = s16[s1*32 + lane];
        uint2 v2 = s16[s2*32 + lane];
        uint2 v3 = s16[s3*32 + lane];
        float2 a0 = __half22float2(*(__half2*)&v0.x), b0 = __half22float2(*(__half2*)&v0.y);
        float2 a1 = __half22float2(*(__half2*)&v1.x), b1 = __half22float2(*(__half2*)&v1.y);
        float2 a2 = __half22float2(*(__half2*)&v2.x), b2 = __half22float2(*(__half2*)&v2.y);
        float2 a3 = __half22float2(*(__half2*)&v3.x), b3 = __half22float2(*(__half2*)&v3.y);
        aA.x += a0.x + a1.x + a2.x + a3.x;
        aA.y += a0.y + a1.y + a2.y + a3.y;
        aA.z += b0.x + b1.x + b2.x + b3.x;
        aA.w += b0.y + b1.y + b2.y + b3.y;
    }
    for (; e < eE; e++) {
        int s0 = g_col[e];
        uint2 v0 = s16[s0*32 + lane];
        float2 a0 = __half22float2(*(__half2*)&v0.x), b0 = __half22float2(*(__half2*)&v0.y);
        aA.x += a0.x; aA.y += a0.y; aA.z += b0.x; aA.w += b0.y;
    }
    ((float4*)ua)[warp*32 + lane] = aA;
}

// agg set B: ub = t + sum x16[src]
__global__ void aggB_kernel(const float* __restrict__ t, float* __restrict__ ub) {
    int warp = (blockIdx.x*blockDim.x + threadIdx.x) >> 5;
    int lane = threadIdx.x & 31;
    if (warp >= NN) return;
    const float4* t4 = (const float4*)t;
    const uint2* s16 = (const uint2*)g_x16;
    float4 aB = t4[warp*32 + lane];
    int e = g_off[NN + warp], eE = g_off[NN + warp + 1];
    for (; e + 3 < eE; e += 4) {
        int s0 = g_col[e], s1 = g_col[e+1], s2 = g_col[e+2], s3 = g_col[e+3];
        uint2 v0 = s16[s0*32 + lane];
        uint2 v1 = s16[s1*32 + lane];
        uint2 v2 = s16[s2*32 + lane];
        uint2 v3 = s16[s3*32 + lane];
        float2 a0 = __half22float2(*(__half2*)&v0.x), b0 = __half22float2(*(__half2*)&v0.y);
        float2 a1 = __half22float2(*(__half2*)&v1.x), b1 = __half22float2(*(__half2*)&v1.y);
        float2 a2 = __half22float2(*(__half2*)&v2.x), b2 = __half22float2(*(__half2*)&v2.y);
        float2 a3 = __half22float2(*(__half2*)&v3.x), b3 = __half22float2(*(__half2*)&v3.y);
        aB.x += a0.x + a1.x + a2.x + a3.x;
        aB.y += a0.y + a1.y + a2.y + a3.y;
        aB.z += b0.x + b1.x + b2.x + b3.x;
        aB.w += b0.y + b1.y + b2.y + b3.y;
    }
    for (; e < eE; e++) {
        int s0 = g_col[e];
        uint2 v0 = s16[s0*32 + lane];
        float2 a0 = __half22float2(*(__half2*)&v0.x), b0 = __half22float2(*(__half2*)&v0.y);
        aB.x += a0.x; aB.y += a0.y; aB.z += b0.x; aB.w += b0.y;
    }
    ((float4*)ub)[warp*32 + lane] = aB;
}

// ---------------- launcher ----------------
extern "C" void kernel_launch(void* const* d_in, const int* in_sizes, int n_in,
                              void* d_out, int out_size) {
    const float* x   = (const float*)d_in[0];
    const float* t   = (const float*)d_in[1];
    const int*   et  = (const int*)d_in[2];
    const int*   ex  = (const int*)d_in[3];
    const float* W1a = (const float*)d_in[4];
    const float* b1a = (const float*)d_in[5];
    const float* W2a = (const float*)d_in[6];
    const float* b2a = (const float*)d_in[7];
    const float* W1b = (const float*)d_in[8];
    const float* b1b = (const float*)d_in[9];
    const float* W2b = (const float*)d_in[10];
    const float* b2b = (const float*)d_in[11];
    const float* Wo  = (const float*)d_in[12];
    const float* bo  = (const float*)d_in[13];
    const float* lng = (const float*)d_in[14];
    const float* lnb = (const float*)d_in[15];
    const float* Wf1 = (const float*)d_in[16];
    const float* bf1 = (const float*)d_in[17];
    const float* Wf2 = (const float*)d_in[18];
    const float* bf2 = (const float*)d_in[19];
    float* out = (float*)d_out;

    float *pua, *pub;
    uint4* pwf;
    cudaGetSymbolAddress((void**)&pua, g_ua);
    cudaGetSymbolAddress((void**)&pub, g_ub);
    cudaGetSymbolAddress((void**)&pwf, g_wfrag);

    cudaFuncSetAttribute(fc_x_mm,       cudaFuncAttributeMaxDynamicSharedMemorySize, SMEM_MM);
    cudaFuncSetAttribute(gin_a_mm,      cudaFuncAttributeMaxDynamicSharedMemorySize, SMEM_MM);
    cudaFuncSetAttribute(fused_rest_mm, cudaFuncAttributeMaxDynamicSharedMemorySize, SMEM_MM);

    cudaStream_t side;
    cudaStreamCreateWithFlags(&side, cudaStreamNonBlocking);
    cudaEvent_t eFork, eCv, eA, eG;
    cudaEventCreateWithFlags(&eFork, cudaEventDisableTiming);
    cudaEventCreateWithFlags(&eCv, cudaEventDisableTiming);
    cudaEventCreateWithFlags(&eA, cudaEventDisableTiming);
    cudaEventCreateWithFlags(&eG, cudaEventDisableTiming);

    cudaEventRecord(eFork, 0);
    cudaStreamWaitEvent(side, eFork, 0);

    // side: fp16 conversion -> weight prep -> fc_x
    conv16_kernel<<<(NN*64 + 255)/256, 256, 0, side>>>(t, x);
    cudaEventRecord(eCv, side);
    prep_w<<<(7*4096 + 255)/256, 256, 0, side>>>(W1a, W2a, W1b, W2b, Wo, Wf1, Wf2);
    fc_x_mm<<<NBLK_MM, MMT, SMEM_MM, side>>>(x, pwf, bf1, bf2, out);

    // main: CSR build, set A first
    zero_cnt_kernel<<<(TWO_N + 1023)/1024, 1024>>>();
    hist_kernel<<<(EE + 255)/256, 256>>>(et, ex);
    scan1_kernel<<<NSB, SCAN_B>>>();
    scan2_kernel<<<1, 256>>>();
    scan3_kernel<<<(TWO_N + 1 + 255)/256, 256>>>();
    fillA_kernel<<<(EE + 255)/256, 256>>>(et);
    cudaStreamWaitEvent(0, eCv, 0);
    aggA_kernel<<<(NN + 7)/8, 256>>>(t, pua);
    cudaEventRecord(eA, 0);

    // side: gin_a overlaps main's fillB+aggB
    cudaStreamWaitEvent(side, eA, 0);
    gin_a_mm<<<NBLK_MM, MMT, SMEM_MM, side>>>(pua, t, pwf, b1a, b2a);
    cudaEventRecord(eG, side);

    // main: set B
    fillB_kernel<<<(EE + 255)/256, 256>>>(ex);
    aggB_kernel<<<(NN + 7)/8, 256>>>(t, pub);

    // join: fused_rest needs gin_a partial + ub
    cudaStreamWaitEvent(0, eG, 0);
    fused_rest_mm<<<NBLK_MM, MMT, SMEM_MM>>>(pua, pub, pwf,
        b1b, b2b, bo, lng, lnb, out + (size_t)NN*DD);

    cudaEventDestroy(eFork);
    cudaEventDestroy(eCv);
    cudaEventDestroy(eA);
    cudaEventDestroy(eG);
    cudaStreamDestroy(side);
}

// round 16
// speedup vs baseline: 1.0645x; 1.0095x over previous
#include <cuda_runtime.h>
#include <cuda_fp16.h>

typedef unsigned long long ull;
typedef unsigned int u32;

#define NN 50000
#define DD 128
#define EE 1600000
#define TWO_N (2*NN)
#define SCAN_B 512
#define NSB ((TWO_N + SCAN_B - 1)/SCAN_B)
#define MT 128
#define NBLK_MM ((NN + MT - 1)/MT)   // 391
#define MMT 256

#define S_AHI 0
#define S_ALO 32768
#define S_B   65536
#define S_BIAS 98304
#define SMEM_MM 102400

#define WI_W1A 0
#define WI_W2A 1
#define WI_W1B 2
#define WI_W2B 3
#define WI_WO  4
#define WI_WF1 5
#define WI_WF2 6

// ---------------- scratch ----------------
__device__ int   g_cnt[TWO_N];
__device__ int   g_off[TWO_N + 1];
__device__ int   g_bsum[NSB];
__device__ int   g_col[2*EE];
__device__ float g_ua[NN*DD];
__device__ float g_ub[NN*DD];
__device__ uint4 g_wfrag[7*4096];
__device__ u32   g_t16[NN*64];
__device__ u32   g_x16[NN*64];

// ---------------- bf16 helpers ----------------
__device__ __forceinline__ u32 pkbf(float lo, float hi) {
    u32 r; asm("cvt.rn.bf16x2.f32 %0, %1, %2;" : "=r"(r) : "f"(hi), "f"(lo)); return r;
}
__device__ __forceinline__ float bf_lo(u32 p) { return __uint_as_float(p << 16); }
__device__ __forceinline__ float bf_hi(u32 p) { return __uint_as_float(p & 0xffff0000u); }

#define MMA4(d, a0, a1, a2, a3, b0, b1) \
    asm volatile("mma.sync.aligned.m16n8k16.row.col.f32.bf16.bf16.f32 " \
        "{%0,%1,%2,%3}, {%4,%5,%6,%7}, {%8,%9}, {%0,%1,%2,%3};" \
        : "+f"((d)[0]), "+f"((d)[1]), "+f"((d)[2]), "+f"((d)[3]) \
        : "r"(a0), "r"(a1), "r"(a2), "r"(a3), "r"(b0), "r"(b1))

// ---------------- fp16 conversion (one-time) ----------------
__global__ void conv16_kernel(const float* __restrict__ t, const float* __restrict__ x) {
    int i = blockIdx.x*blockDim.x + threadIdx.x;
    if (i < NN*64) {
        float2 tv = ((const float2*)t)[i];
        float2 xv = ((const float2*)x)[i];
        __half2 th = __floats2half2_rn(tv.x, tv.y);
        __half2 xh = __floats2half2_rn(xv.x, xv.y);
        g_t16[i] = *(u32*)&th;
        g_x16[i] = *(u32*)&xh;
    }
}

// ---------------- one-time weight fragment prep ----------------
__global__ void prep_w(const float* __restrict__ W1a, const float* __restrict__ W2a,
                       const float* __restrict__ W1b, const float* __restrict__ W2b,
                       const float* __restrict__ Wo,  const float* __restrict__ Wf1,
                       const float* __restrict__ Wf2) {
    int idx = blockIdx.x*blockDim.x + threadIdx.x;
    if (idx >= 7*4096) return;
    const float* Ws[7] = {W1a, W2a, W1b, W2b, Wo, Wf1, Wf2};
    int w = idx >> 12;
    int rem = idx & 4095;
    int half = rem >> 11;
    int s = rem & 2047;
    int lane = s & 31, nt = (s >> 5) & 7, ks = s >> 8;
    int g = lane >> 2, c = lane & 3;
    const float* W = Ws[w];
    int n = half*64 + nt*8 + g;
    int k0 = ks*16 + 2*c;
    float w00 = W[(size_t)k0*128 + n];
    float w01 = W[(size_t)(k0+1)*128 + n];
    float w10 = W[(size_t)(k0+8)*128 + n];
    float w11 = W[(size_t)(k0+9)*128 + n];
    u32 bh0 = pkbf(w00, w01);
    u32 bh1 = pkbf(w10, w11);
    u32 bl0 = pkbf(w00 - bf_lo(bh0), w01 - bf_hi(bh0));
    u32 bl1 = pkbf(w10 - bf_lo(bh1), w11 - bf_hi(bh1));
    g_wfrag[idx] = make_uint4(bh0, bh1, bl0, bl1);
}

// ---------------- fragment staging ----------------
__device__ __forceinline__ void stage_A(u32* sAhi, u32* sAlo, const float* A, int row0) {
    for (int idx = threadIdx.x; idx < 128*64; idx += MMT) {
        int r = idx >> 6, j = idx & 63;
        int row = row0 + r;
        float v0 = 0.f, v1 = 0.f;
        if (row < NN) {
            float2 vv = *(const float2*)(A + (size_t)row*128 + 2*j);
            v0 = vv.x; v1 = vv.y;
        }
        u32 hp = pkbf(v0, v1);
        u32 lp = pkbf(v0 - bf_lo(hp), v1 - bf_hi(hp));
        int ks = j >> 3;
        int reg = ((r >> 3) & 1) | ((j & 4) ? 2 : 0);
        int ln  = (r & 7)*4 + (j & 3);
        int mt  = r >> 4;
        int o = ((ks*8 + mt)*32 + ln)*4 + reg;
        sAhi[o] = hp; sAlo[o] = lp;
    }
}

__device__ __forceinline__ void stage_W(u32* sB, const uint4* __restrict__ gw) {
    uint4* dst = (uint4*)sB;
    #pragma unroll
    for (int i = threadIdx.x; i < 2048; i += MMT) dst[i] = gw[i];
}

__device__ __forceinline__ void mma_half(const u32* sAhi, const u32* sAlo, const u32* sB,
                                         int wid, int lane, float acc[8][4]) {
    #pragma unroll
    for (int nt = 0; nt < 8; nt++)
        #pragma unroll
        for (int q = 0; q < 4; q++) acc[nt][q] = 0.f;
    #pragma unroll
    for (int ks = 0; ks < 8; ks++) {
        uint4 ah = *(const uint4*)(sAhi + ((ks*8 + wid)*32 + lane)*4);
        uint4 al = *(const uint4*)(sAlo + ((ks*8 + wid)*32 + lane)*4);
        #pragma unroll
        for (int nt = 0; nt < 8; nt++) {
            uint4 b = *(const uint4*)(sB + ((ks*8 + nt)*32 + lane)*4);
            MMA4(acc[nt], ah.x, ah.y, ah.z, ah.w, b.x, b.y);
            MMA4(acc[nt], al.x, al.y, al.z, al.w, b.x, b.y);
            MMA4(acc[nt], ah.x, ah.y, ah.z, ah.w, b.z, b.w);
        }
    }
}

__device__ __forceinline__ void layer(u32* sAhi, u32* sAlo, u32* sB,
                                      const uint4* __restrict__ gw,
                                      int wid, int lane,
                                      float acc0[8][4], float acc1[8][4]) {
    __syncthreads();
    stage_W(sB, gw);
    __syncthreads();
    mma_half(sAhi, sAlo, sB, wid, lane, acc0);
    __syncthreads();
    stage_W(sB, gw + 2048);
    __syncthreads();
    mma_half(sAhi, sAlo, sB, wid, lane, acc1);
}

__device__ __forceinline__ void write_H(u32* sAhi, u32* sAlo,
                                        float acc0[8][4], float acc1[8][4],
                                        const float* bias, int wid, int lane) {
    int g = lane >> 2, c = lane & 3;
    #pragma unroll
    for (int half = 0; half < 2; half++) {
        float (*acc)[4] = half ? acc1 : acc0;
        #pragma unroll
        for (int nt = 0; nt < 8; nt++) {
            int col = half*64 + nt*8 + 2*c;
            float b0 = bias[col], b1 = bias[col+1];
            int j = col >> 1;
            int ks = j >> 3;
            int ln = g*4 + (j & 3);
            int base = ((ks*8 + wid)*32 + ln)*4 + ((j & 4) ? 2 : 0);
            #pragma unroll
            for (int pr = 0; pr < 2; pr++) {
                float v0 = fmaxf(acc[nt][pr*2]   + b0, 0.f);
                float v1 = fmaxf(acc[nt][pr*2+1] + b1, 0.f);
                u32 hp = pkbf(v0, v1);
                u32 lp = pkbf(v0 - bf_lo(hp), v1 - bf_hi(hp));
                sAhi[base + pr] = hp;
                sAlo[base + pr] = lp;
            }
        }
    }
}

// ================= fc_x =================
__global__ __launch_bounds__(MMT, 2) void fc_x_mm(
    const float* __restrict__ X,
    const uint4* __restrict__ gwf,
    const float* __restrict__ B1, const float* __restrict__ B2,
    float* __restrict__ OUT)
{
    extern __shared__ char smc[];
    u32* sAhi = (u32*)(smc + S_AHI);
    u32* sAlo = (u32*)(smc + S_ALO);
    u32* sB   = (u32*)(smc + S_B);
    float* sb1 = (float*)(smc + S_BIAS);
    float* sb2 = (float*)(smc + S_BIAS + 512);

    const int tid = threadIdx.x;
    const int wid = tid >> 5, lane = tid & 31;
    const int row0 = blockIdx.x * MT;
    if (tid < 128) { sb1[tid] = B1[tid]; sb2[tid] = B2[tid]; }
    stage_A(sAhi, sAlo, X, row0);

    float acc0[8][4], acc1[8][4];
    layer(sAhi, sAlo, sB, gwf + WI_WF1*4096, wid, lane, acc0, acc1);
    write_H(sAhi, sAlo, acc0, acc1, sb1, wid, lane);
    layer(sAhi, sAlo, sB, gwf + WI_WF2*4096, wid, lane, acc0, acc1);

    int g = lane >> 2, c = lane & 3;
    int r0 = row0 + wid*16 + g;
    #pragma unroll
    for (int half = 0; half < 2; half++) {
        float (*acc)[4] = half ? acc1 : acc0;
        #pragma unroll
        for (int nt = 0; nt < 8; nt++) {
            int col = half*64 + nt*8 + 2*c;
            float b0 = sb2[col], b1 = sb2[col+1];
            #pragma unroll
            for (int pr = 0; pr < 2; pr++) {
                int row = r0 + pr*8;
                if (row < NN) {
                    float2 xv = *(const float2*)(X + (size_t)row*128 + col);
                    float2 o;
                    o.x = xv.x + acc[nt][pr*2]   + b0;
                    o.y = xv.y + acc[nt][pr*2+1] + b1;
                    *(float2*)(OUT + (size_t)row*128 + col) = o;
                }
            }
        }
    }
}

// ================= gin_a: partial = t + mlp_a(ua) + b2a -> g_ua =================
__global__ __launch_bounds__(MMT, 2) void gin_a_mm(
    float* __restrict__ ua, const float* __restrict__ t,
    const uint4* __restrict__ gwf,
    const float* __restrict__ b1a, const float* __restrict__ b2a)
{
    extern __shared__ char smc[];
    u32* sAhi = (u32*)(smc + S_AHI);
    u32* sAlo = (u32*)(smc + S_ALO);
    u32* sB   = (u32*)(smc + S_B);
    float* s_b1a = (float*)(smc + S_BIAS);
    float* s_b2a = (float*)(smc + S_BIAS + 512);

    const int tid = threadIdx.x;
    const int wid = tid >> 5, lane = tid & 31;
    const int g = lane >> 2, c = lane & 3;
    const int row0 = blockIdx.x * MT;
    const int r0 = row0 + wid*16 + g;

    if (tid < 128) { s_b1a[tid] = b1a[tid]; s_b2a[tid] = b2a[tid]; }
    stage_A(sAhi, sAlo, ua, row0);

    float acc0[8][4], acc1[8][4];
    layer(sAhi, sAlo, sB, gwf + WI_W1A*4096, wid, lane, acc0, acc1);
    write_H(sAhi, sAlo, acc0, acc1, s_b1a, wid, lane);
    layer(sAhi, sAlo, sB, gwf + WI_W2A*4096, wid, lane, acc0, acc1);

    #pragma unroll
    for (int half = 0; half < 2; half++) {
        float (*acc)[4] = half ? acc1 : acc0;
        #pragma unroll
        for (int nt = 0; nt < 8; nt++) {
            int col = half*64 + nt*8 + 2*c;
            float b0 = s_b2a[col], b1 = s_b2a[col+1];
            #pragma unroll
            for (int pr = 0; pr < 2; pr++) {
                int row = r0 + pr*8;
                if (row < NN) {
                    float2 tv = *(const float2*)(t + (size_t)row*128 + col);
                    float2 o;
                    o.x = tv.x + acc[nt][pr*2]   + b0;
                    o.y = tv.y + acc[nt][pr*2+1] + b1;
                    *(float2*)(ua + (size_t)row*128 + col) = o;
                }
            }
        }
    }
}

// ================= fused_rest: gin_b + t2 + out-Linear + LN =================
__global__ __launch_bounds__(MMT, 2) void fused_rest_mm(
    const float* __restrict__ partial, const float* __restrict__ ub,
    const uint4* __restrict__ gwf,
    const float* __restrict__ b1b, const float* __restrict__ b2b,
    const float* __restrict__ bo,
    const float* __restrict__ lng, const float* __restrict__ lnb,
    float* __restrict__ OUT)
{
    extern __shared__ char smc[];
    u32* sAhi = (u32*)(smc + S_AHI);
    u32* sAlo = (u32*)(smc + S_ALO);
    u32* sB   = (u32*)(smc + S_B);
    float* s_b1b = (float*)(smc + S_BIAS);
    float* s_b2b = (float*)(smc + S_BIAS + 512);
    float* s_bo  = (float*)(smc + S_BIAS + 1024);
    float* s_g   = (float*)(smc + S_BIAS + 1536);
    float* s_be  = (float*)(smc + S_BIAS + 2048);

    const int tid = threadIdx.x;
    const int wid = tid >> 5, lane = tid & 31;
    const int g = lane >> 2, c = lane & 3;
    const int row0 = blockIdx.x * MT;
    const int r0 = row0 + wid*16 + g;

    if (tid < 128) {
        s_b1b[tid] = b1b[tid]; s_b2b[tid] = b2b[tid];
        s_bo[tid]  = bo[tid];  s_g[tid]   = lng[tid]; s_be[tid] = lnb[tid];
    }
    stage_A(sAhi, sAlo, ub, row0);

    float acc0[8][4], acc1[8][4];
    layer(sAhi, sAlo, sB, gwf + WI_W1B*4096, wid, lane, acc0, acc1);
    write_H(sAhi, sAlo, acc0, acc1, s_b1b, wid, lane);
    layer(sAhi, sAlo, sB, gwf + WI_W2B*4096, wid, lane, acc0, acc1);

    #pragma unroll
    for (int half = 0; half < 2; half++) {
        float (*acc)[4] = half ? acc1 : acc0;
        #pragma unroll
        for (int nt = 0; nt < 8; nt++) {
            int col = half*64 + nt*8 + 2*c;
            float b0 = s_b2b[col], b1 = s_b2b[col+1];
            int j = col >> 1;
            int ks = j >> 3;
            int ln = g*4 + (j & 3);
            int base = ((ks*8 + wid)*32 + ln)*4 + ((j & 4) ? 2 : 0);
            #pragma unroll
            for (int pr = 0; pr < 2; pr++) {
                int row = r0 + pr*8;
                float p0 = 0.f, p1 = 0.f;
                if (row < NN) {
                    float2 pv = *(const float2*)(partial + (size_t)row*128 + col);
                    p0 = pv.x; p1 = pv.y;
                }
                float v0 = fmaxf(p0 + acc[nt][pr*2]   + b0, 0.f);
                float v1 = fmaxf(p1 + acc[nt][pr*2+1] + b1, 0.f);
                u32 hp = pkbf(v0, v1);
                u32 lp = pkbf(v0 - bf_lo(hp), v1 - bf_hi(hp));
                sAhi[base + pr] = hp;
                sAlo[base + pr] = lp;
            }
        }
    }

    layer(sAhi, sAlo, sB, gwf + WI_WO*4096, wid, lane, acc0, acc1);

    float s0 = 0.f, q0 = 0.f, s1 = 0.f, q1 = 0.f;
    #pragma unroll
    for (int half = 0; half < 2; half++) {
        float (*acc)[4] = half ? acc1 : acc0;
        #pragma unroll
        for (int nt = 0; nt < 8; nt++) {
            int col = half*64 + nt*8 + 2*c;
            float b0 = s_bo[col], b1 = s_bo[col+1];
            float z00 = fmaxf(acc[nt][0] + b0, 0.f);
            float z01 = fmaxf(acc[nt][1] + b1, 0.f);
            float z10 = fmaxf(acc[nt][2] + b0, 0.f);
            float z11 = fmaxf(acc[nt][3] + b1, 0.f);
            s0 += z00 + z01; q0 += z00*z00 + z01*z01;
            s1 += z10 + z11; q1 += z10*z10 + z11*z11;
        }
    }
    #pragma unroll
    for (int d = 1; d <= 2; d <<= 1) {
        s0 += __shfl_xor_sync(0xffffffffu, s0, d);
        q0 += __shfl_xor_sync(0xffffffffu, q0, d);
        s1 += __shfl_xor_sync(0xffffffffu, s1, d);
        q1 += __shfl_xor_sync(0xffffffffu, q1, d);
    }
    float m0 = s0*(1.f/128.f), m1 = s1*(1.f/128.f);
    float rs0 = rsqrtf(q0*(1.f/128.f) - m0*m0 + 1e-5f);
    float rs1 = rsqrtf(q1*(1.f/128.f) - m1*m1 + 1e-5f);

    #pragma unroll
    for (int half = 0; half < 2; half++) {
        float (*acc)[4] = half ? acc1 : acc0;
        #pragma unroll
        for (int nt = 0; nt < 8; nt++) {
            int col = half*64 + nt*8 + 2*c;
            float b0 = s_bo[col], b1 = s_bo[col+1];
            float g0 = s_g[col], g1 = s_g[col+1];
            float e0 = s_be[col], e1 = s_be[col+1];
            int j = col >> 1;
            int ks = j >> 3;
            int ln = g*4 + (j & 3);
            int base = ((ks*8 + wid)*32 + ln)*4 + ((j & 4) ? 2 : 0);
            #pragma unroll
            for (int pr = 0; pr < 2; pr++) {
                int row = r0 + pr*8;
                if (row < NN) {
                    float mm = pr ? m1 : m0;
                    float rr = pr ? rs1 : rs0;
                    u32 hp = sAhi[base + pr], lp = sAlo[base + pr];
                    float t20 = bf_lo(hp) + bf_lo(lp);
                    float t21 = bf_hi(hp) + bf_hi(lp);
                    float z0 = fmaxf(acc[nt][pr*2]   + b0, 0.f);
                    float z1 = fmaxf(acc[nt][pr*2+1] + b1, 0.f);
                    float2 o;
                    o.x = t20 + (z0 - mm)*rr*g0 + e0;
                    o.y = t21 + (z1 - mm)*rr*g1 + e1;
                    *(float2*)(OUT + (size_t)row*128 + col) = o;
                }
            }
        }
    }
}

// ---------------- CSR construction ----------------
__global__ void zero_cnt_kernel() {
    int i = blockIdx.x*blockDim.x + threadIdx.x;
    if (i < TWO_N) g_cnt[i] = 0;
}

__global__ void hist_kernel(const int* __restrict__ et, const int* __restrict__ ex) {
    int i = blockIdx.x*blockDim.x + threadIdx.x;
    if (i < EE) {
        atomicAdd(&g_cnt[et[EE + i]], 1);
        atomicAdd(&g_cnt[NN + ex[EE + i]], 1);
    }
}

__global__ void scan1_kernel() {
    __shared__ int s[SCAN_B];
    int i = blockIdx.x*SCAN_B + threadIdx.x;
    int v = (i < TWO_N) ? g_cnt[i] : 0;
    s[threadIdx.x] = v;
    __syncthreads();
    #pragma unroll
    for (int d = 1; d < SCAN_B; d <<= 1) {
        int tv = (threadIdx.x >= d) ? s[threadIdx.x - d] : 0;
        __syncthreads();
        s[threadIdx.x] += tv;
        __syncthreads();
    }
    if (i < TWO_N) g_off[i + 1] = s[threadIdx.x];
    if (threadIdx.x == SCAN_B - 1) g_bsum[blockIdx.x] = s[SCAN_B - 1];
}

__global__ void scan2_kernel() {
    __shared__ int s[256];
    int v = (threadIdx.x < NSB) ? g_bsum[threadIdx.x] : 0;
    s[threadIdx.x] = v;
    __syncthreads();
    #pragma unroll
    for (int d = 1; d < 256; d <<= 1) {
        int tv = (threadIdx.x >= d) ? s[threadIdx.x - d] : 0;
        __syncthreads();
        s[threadIdx.x] += tv;
        __syncthreads();
    }
    if (threadIdx.x < NSB) g_bsum[threadIdx.x] = s[threadIdx.x] - v;
}

__global__ void scan3_kernel() {
    int i = blockIdx.x*blockDim.x + threadIdx.x;
    if (i == 0) { g_off[0] = 0; g_cnt[0] = 0; }
    else if (i <= TWO_N) {
        int v = g_off[i] + g_bsum[(i - 1) / SCAN_B];
        g_off[i] = v;
        if (i < TWO_N) g_cnt[i] = v;
    }
}

__global__ void fillA_kernel(const int* __restrict__ et) {
    int i = blockIdx.x*blockDim.x + threadIdx.x;
    if (i < EE) {
        int p = atomicAdd(&g_cnt[et[EE + i]], 1);
        g_col[p] = et[i];
    }
}

__global__ void fillB_kernel(const int* __restrict__ ex) {
    int i = blockIdx.x*blockDim.x + threadIdx.x;
    if (i < EE) {
        int q = atomicAdd(&g_cnt[NN + ex[EE + i]], 1);
        g_col[q] = ex[i];
    }
}

// agg set A: ua = t + sum t16[src]
__global__ void aggA_kernel(const float* __restrict__ t, float* __restrict__ ua) {
    int warp = (blockIdx.x*blockDim.x + threadIdx.x) >> 5;
    int lane = threadIdx.x & 31;
    if (warp >= NN) return;
    const float4* t4 = (const float4*)t;
    const uint2* s16 = (const uint2*)g_t16;
    float4 aA = t4[warp*32 + lane];
    int e = g_off[warp], eE = g_off[warp + 1];
    for (; e + 3 < eE; e += 4) {
        int s0 = g_col[e], s1 = g_col[e+1], s2 = g_col[e+2], s3 = g_col[e+3];
        uint2 v0 = s16[s0*32 + lane];
        uint2 v1 = s16[s1*32 + lane];
        uint2 v2 = s16[s2*32 + lane];
        uint2 v3 = s16[s3*32 + lane];
        float2 a0 = __half22float2(*(__half2*)&v0.x), b0 = __half22float2(*(__half2*)&v0.y);
        float2 a1 = __half22float2(*(__half2*)&v1.x), b1 = __half22float2(*(__half2*)&v1.y);
        float2 a2 = __half22float2(*(__half2*)&v2.x), b2 = __half22float2(*(__half2*)&v2.y);
        float2 a3 = __half22float2(*(__half2*)&v3.x), b3 = __half22float2(*(__half2*)&v3.y);
        aA.x += a0.x + a1.x + a2.x + a3.x;
        aA.y += a0.y + a1.y + a2.y + a3.y;
        aA.z += b0.x + b1.x + b2.x + b3.x;
        aA.w += b0.y + b1.y + b2.y + b3.y;
    }
    for (; e < eE; e++) {
        int s0 = g_col[e];
        uint2 v0 = s16[s0*32 + lane];
        float2 a0 = __half22float2(*(__half2*)&v0.x), b0 = __half22float2(*(__half2*)&v0.y);
        aA.x += a0.x; aA.y += a0.y; aA.z += b0.x; aA.w += b0.y;
    }
    ((float4*)ua)[warp*32 + lane] = aA;
}

// agg set B: ub = t + sum x16[src]
__global__ void aggB_kernel(const float* __restrict__ t, float* __restrict__ ub) {
    int warp = (blockIdx.x*blockDim.x + threadIdx.x) >> 5;
    int lane = threadIdx.x & 31;
    if (warp >= NN) return;
    const float4* t4 = (const float4*)t;
    const uint2* s16 = (const uint2*)g_x16;
    float4 aB = t4[warp*32 + lane];
    int e = g_off[NN + warp], eE = g_off[NN + warp + 1];
    for (; e + 3 < eE; e += 4) {
        int s0 = g_col[e], s1 = g_col[e+1], s2 = g_col[e+2], s3 = g_col[e+3];
        uint2 v0 = s16[s0*32 + lane];
        uint2 v1 = s16[s1*32 + lane];
        uint2 v2 = s16[s2*32 + lane];
        uint2 v3 = s16[s3*32 + lane];
        float2 a0 = __half22float2(*(__half2*)&v0.x), b0 = __half22float2(*(__half2*)&v0.y);
        float2 a1 = __half22float2(*(__half2*)&v1.x), b1 = __half22float2(*(__half2*)&v1.y);
        float2 a2 = __half22float2(*(__half2*)&v2.x), b2 = __half22float2(*(__half2*)&v2.y);
        float2 a3 = __half22float2(*(__half2*)&v3.x), b3 = __half22float2(*(__half2*)&v3.y);
        aB.x += a0.x + a1.x + a2.x + a3.x;
        aB.y += a0.y + a1.y + a2.y + a3.y;
        aB.z += b0.x + b1.x + b2.x + b3.x;
        aB.w += b0.y + b1.y + b2.y + b3.y;
    }
    for (; e < eE; e++) {
        int s0 = g_col[e];
        uint2 v0 = s16[s0*32 + lane];
        float2 a0 = __half22float2(*(__half2*)&v0.x), b0 = __half22float2(*(__half2*)&v0.y);
        aB.x += a0.x; aB.y += a0.y; aB.z += b0.x; aB.w += b0.y;
    }
    ((float4*)ub)[warp*32 + lane] = aB;
}

// ---------------- launcher ----------------
extern "C" void kernel_launch(void* const* d_in, const int* in_sizes, int n_in,
                              void* d_out, int out_size) {
    const float* x   = (const float*)d_in[0];
    const float* t   = (const float*)d_in[1];
    const int*   et  = (const int*)d_in[2];
    const int*   ex  = (const int*)d_in[3];
    const float* W1a = (const float*)d_in[4];
    const float* b1a = (const float*)d_in[5];
    const float* W2a = (const float*)d_in[6];
    const float* b2a = (const float*)d_in[7];
    const float* W1b = (const float*)d_in[8];
    const float* b1b = (const float*)d_in[9];
    const float* W2b = (const float*)d_in[10];
    const float* b2b = (const float*)d_in[11];
    const float* Wo  = (const float*)d_in[12];
    const float* bo  = (const float*)d_in[13];
    const float* lng = (const float*)d_in[14];
    const float* lnb = (const float*)d_in[15];
    const float* Wf1 = (const float*)d_in[16];
    const float* bf1 = (const float*)d_in[17];
    const float* Wf2 = (const float*)d_in[18];
    const float* bf2 = (const float*)d_in[19];
    float* out = (float*)d_out;

    float *pua, *pub;
    uint4* pwf;
    cudaGetSymbolAddress((void**)&pua, g_ua);
    cudaGetSymbolAddress((void**)&pub, g_ub);
    cudaGetSymbolAddress((void**)&pwf, g_wfrag);

    cudaFuncSetAttribute(fc_x_mm,       cudaFuncAttributeMaxDynamicSharedMemorySize, SMEM_MM);
    cudaFuncSetAttribute(gin_a_mm,      cudaFuncAttributeMaxDynamicSharedMemorySize, SMEM_MM);
    cudaFuncSetAttribute(fused_rest_mm, cudaFuncAttributeMaxDynamicSharedMemorySize, SMEM_MM);

    cudaStream_t side;
    cudaStreamCreateWithFlags(&side, cudaStreamNonBlocking);
    cudaEvent_t eFork, eCv, eS3, eFB, eA, eG;
    cudaEventCreateWithFlags(&eFork, cudaEventDisableTiming);
    cudaEventCreateWithFlags(&eCv, cudaEventDisableTiming);
    cudaEventCreateWithFlags(&eS3, cudaEventDisableTiming);
    cudaEventCreateWithFlags(&eFB, cudaEventDisableTiming);
    cudaEventCreateWithFlags(&eA, cudaEventDisableTiming);
    cudaEventCreateWithFlags(&eG, cudaEventDisableTiming);

    cudaEventRecord(eFork, 0);
    cudaStreamWaitEvent(side, eFork, 0);

    // side: fp16 conversion -> weight prep -> fc_x
    conv16_kernel<<<(NN*64 + 255)/256, 256, 0, side>>>(t, x);
    cudaEventRecord(eCv, side);
    prep_w<<<(7*4096 + 255)/256, 256, 0, side>>>(W1a, W2a, W1b, W2b, Wo, Wf1, Wf2);
    fc_x_mm<<<NBLK_MM, MMT, SMEM_MM, side>>>(x, pwf, bf1, bf2, out);

    // main: CSR build
    zero_cnt_kernel<<<(TWO_N + 1023)/1024, 1024>>>();
    hist_kernel<<<(EE + 255)/256, 256>>>(et, ex);
    scan1_kernel<<<NSB, SCAN_B>>>();
    scan2_kernel<<<1, 256>>>();
    scan3_kernel<<<(TWO_N + 1 + 255)/256, 256>>>();
    cudaEventRecord(eS3, 0);

    // side: fillB as soon as scan3 done (overlaps fillA + aggA on main)
    cudaStreamWaitEvent(side, eS3, 0);
    fillB_kernel<<<(EE + 255)/256, 256, 0, side>>>(ex);
    cudaEventRecord(eFB, side);

    // main: fillA -> aggA
    fillA_kernel<<<(EE + 255)/256, 256>>>(et);
    cudaStreamWaitEvent(0, eCv, 0);
    aggA_kernel<<<(NN + 7)/8, 256>>>(t, pua);
    cudaEventRecord(eA, 0);

    // side: gin_a overlaps main's aggB
    cudaStreamWaitEvent(side, eA, 0);
    gin_a_mm<<<NBLK_MM, MMT, SMEM_MM, side>>>(pua, t, pwf, b1a, b2a);
    cudaEventRecord(eG, side);

    // main: aggB (fillB done on side during aggA)
    cudaStreamWaitEvent(0, eFB, 0);
    aggB_kernel<<<(NN + 7)/8, 256>>>(t, pub);

    // join: fused_rest needs gin_a partial + ub
    cudaStreamWaitEvent(0, eG, 0);
    fused_rest_mm<<<NBLK_MM, MMT, SMEM_MM>>>(pua, pub, pwf,
        b1b, b2b, bo, lng, lnb, out + (size_t)NN*DD);

    cudaEventDestroy(eFork);
    cudaEventDestroy(eCv);
    cudaEventDestroy(eS3);
    cudaEventDestroy(eFB);
    cudaEventDestroy(eA);
    cudaEventDestroy(eG);
    cudaStreamDestroy(side);
}

// round 17
// speedup vs baseline: 1.0664x; 1.0018x over previous
#include <cuda_runtime.h>
#include <cuda_fp16.h>

typedef unsigned long long ull;
typedef unsigned int u32;

#define NN 50000
#define DD 128
#define EE 1600000
#define TWO_N (2*NN)
#define SCAN_B 512
#define NSB ((TWO_N + SCAN_B - 1)/SCAN_B)
#define MT 128
#define NBLK_MM ((NN + MT - 1)/MT)   // 391
#define MMT 256

#define S_AHI 0
#define S_ALO 32768
#define S_B   65536
#define S_BIAS 98304
#define SMEM_MM 102400

#define WI_W1A 0
#define WI_W2A 1
#define WI_W1B 2
#define WI_W2B 3
#define WI_WO  4
#define WI_WF1 5
#define WI_WF2 6

// ---------------- scratch ----------------
__device__ int   g_cnt[TWO_N];
__device__ int   g_off[TWO_N + 1];
__device__ int   g_bsum[NSB];
__device__ int   g_col[2*EE];
__device__ float g_ua[NN*DD];
__device__ float g_ub[NN*DD];
__device__ uint4 g_wfrag[7*4096];
__device__ u32   g_t16[NN*64];
__device__ u32   g_x16[NN*64];

// ---------------- bf16 helpers ----------------
__device__ __forceinline__ u32 pkbf(float lo, float hi) {
    u32 r; asm("cvt.rn.bf16x2.f32 %0, %1, %2;" : "=r"(r) : "f"(hi), "f"(lo)); return r;
}
__device__ __forceinline__ float bf_lo(u32 p) { return __uint_as_float(p << 16); }
__device__ __forceinline__ float bf_hi(u32 p) { return __uint_as_float(p & 0xffff0000u); }

#define MMA4(d, a0, a1, a2, a3, b0, b1) \
    asm volatile("mma.sync.aligned.m16n8k16.row.col.f32.bf16.bf16.f32 " \
        "{%0,%1,%2,%3}, {%4,%5,%6,%7}, {%8,%9}, {%0,%1,%2,%3};" \
        : "+f"((d)[0]), "+f"((d)[1]), "+f"((d)[2]), "+f"((d)[3]) \
        : "r"(a0), "r"(a1), "r"(a2), "r"(a3), "r"(b0), "r"(b1))

// ---------------- fp16 conversion (one-time) ----------------
__global__ void conv16_kernel(const float* __restrict__ t, const float* __restrict__ x) {
    int i = blockIdx.x*blockDim.x + threadIdx.x;
    if (i < NN*64) {
        float2 tv = ((const float2*)t)[i];
        float2 xv = ((const float2*)x)[i];
        __half2 th = __floats2half2_rn(tv.x, tv.y);
        __half2 xh = __floats2half2_rn(xv.x, xv.y);
        g_t16[i] = *(u32*)&th;
        g_x16[i] = *(u32*)&xh;
    }
}

// ---------------- one-time weight fragment prep ----------------
__global__ void prep_w(const float* __restrict__ W1a, const float* __restrict__ W2a,
                       const float* __restrict__ W1b, const float* __restrict__ W2b,
                       const float* __restrict__ Wo,  const float* __restrict__ Wf1,
                       const float* __restrict__ Wf2) {
    int idx = blockIdx.x*blockDim.x + threadIdx.x;
    if (idx >= 7*4096) return;
    const float* Ws[7] = {W1a, W2a, W1b, W2b, Wo, Wf1, Wf2};
    int w = idx >> 12;
    int rem = idx & 4095;
    int half = rem >> 11;
    int s = rem & 2047;
    int lane = s & 31, nt = (s >> 5) & 7, ks = s >> 8;
    int g = lane >> 2, c = lane & 3;
    const float* W = Ws[w];
    int n = half*64 + nt*8 + g;
    int k0 = ks*16 + 2*c;
    float w00 = W[(size_t)k0*128 + n];
    float w01 = W[(size_t)(k0+1)*128 + n];
    float w10 = W[(size_t)(k0+8)*128 + n];
    float w11 = W[(size_t)(k0+9)*128 + n];
    u32 bh0 = pkbf(w00, w01);
    u32 bh1 = pkbf(w10, w11);
    u32 bl0 = pkbf(w00 - bf_lo(bh0), w01 - bf_hi(bh0));
    u32 bl1 = pkbf(w10 - bf_lo(bh1), w11 - bf_hi(bh1));
    g_wfrag[idx] = make_uint4(bh0, bh1, bl0, bl1);
}

// ---------------- fragment staging ----------------
__device__ __forceinline__ void stage_A(u32* sAhi, u32* sAlo, const float* A, int row0) {
    for (int idx = threadIdx.x; idx < 128*64; idx += MMT) {
        int r = idx >> 6, j = idx & 63;
        int row = row0 + r;
        float v0 = 0.f, v1 = 0.f;
        if (row < NN) {
            float2 vv = *(const float2*)(A + (size_t)row*128 + 2*j);
            v0 = vv.x; v1 = vv.y;
        }
        u32 hp = pkbf(v0, v1);
        u32 lp = pkbf(v0 - bf_lo(hp), v1 - bf_hi(hp));
        int ks = j >> 3;
        int reg = ((r >> 3) & 1) | ((j & 4) ? 2 : 0);
        int ln  = (r & 7)*4 + (j & 3);
        int mt  = r >> 4;
        int o = ((ks*8 + mt)*32 + ln)*4 + reg;
        sAhi[o] = hp; sAlo[o] = lp;
    }
}

__device__ __forceinline__ void stage_W(u32* sB, const uint4* __restrict__ gw) {
    uint4* dst = (uint4*)sB;
    #pragma unroll
    for (int i = threadIdx.x; i < 2048; i += MMT) dst[i] = gw[i];
}

__device__ __forceinline__ void mma_half(const u32* sAhi, const u32* sAlo, const u32* sB,
                                         int wid, int lane, float acc[8][4]) {
    #pragma unroll
    for (int nt = 0; nt < 8; nt++)
        #pragma unroll
        for (int q = 0; q < 4; q++) acc[nt][q] = 0.f;
    #pragma unroll
    for (int ks = 0; ks < 8; ks++) {
        uint4 ah = *(const uint4*)(sAhi + ((ks*8 + wid)*32 + lane)*4);
        uint4 al = *(const uint4*)(sAlo + ((ks*8 + wid)*32 + lane)*4);
        #pragma unroll
        for (int nt = 0; nt < 8; nt++) {
            uint4 b = *(const uint4*)(sB + ((ks*8 + nt)*32 + lane)*4);
            MMA4(acc[nt], ah.x, ah.y, ah.z, ah.w, b.x, b.y);
            MMA4(acc[nt], al.x, al.y, al.z, al.w, b.x, b.y);
            MMA4(acc[nt], ah.x, ah.y, ah.z, ah.w, b.z, b.w);
        }
    }
}

__device__ __forceinline__ void layer(u32* sAhi, u32* sAlo, u32* sB,
                                      const uint4* __restrict__ gw,
                                      int wid, int lane,
                                      float acc0[8][4], float acc1[8][4]) {
    __syncthreads();
    stage_W(sB, gw);
    __syncthreads();
    mma_half(sAhi, sAlo, sB, wid, lane, acc0);
    __syncthreads();
    stage_W(sB, gw + 2048);
    __syncthreads();
    mma_half(sAhi, sAlo, sB, wid, lane, acc1);
}

__device__ __forceinline__ void write_H(u32* sAhi, u32* sAlo,
                                        float acc0[8][4], float acc1[8][4],
                                        const float* bias, int wid, int lane) {
    int g = lane >> 2, c = lane & 3;
    #pragma unroll
    for (int half = 0; half < 2; half++) {
        float (*acc)[4] = half ? acc1 : acc0;
        #pragma unroll
        for (int nt = 0; nt < 8; nt++) {
            int col = half*64 + nt*8 + 2*c;
            float b0 = bias[col], b1 = bias[col+1];
            int j = col >> 1;
            int ks = j >> 3;
            int ln = g*4 + (j & 3);
            int base = ((ks*8 + wid)*32 + ln)*4 + ((j & 4) ? 2 : 0);
            #pragma unroll
            for (int pr = 0; pr < 2; pr++) {
                float v0 = fmaxf(acc[nt][pr*2]   + b0, 0.f);
                float v1 = fmaxf(acc[nt][pr*2+1] + b1, 0.f);
                u32 hp = pkbf(v0, v1);
                u32 lp = pkbf(v0 - bf_lo(hp), v1 - bf_hi(hp));
                sAhi[base + pr] = hp;
                sAlo[base + pr] = lp;
            }
        }
    }
}

// ================= fc_x =================
__global__ __launch_bounds__(MMT, 2) void fc_x_mm(
    const float* __restrict__ X,
    const uint4* __restrict__ gwf,
    const float* __restrict__ B1, const float* __restrict__ B2,
    float* __restrict__ OUT)
{
    extern __shared__ char smc[];
    u32* sAhi = (u32*)(smc + S_AHI);
    u32* sAlo = (u32*)(smc + S_ALO);
    u32* sB   = (u32*)(smc + S_B);
    float* sb1 = (float*)(smc + S_BIAS);
    float* sb2 = (float*)(smc + S_BIAS + 512);

    const int tid = threadIdx.x;
    const int wid = tid >> 5, lane = tid & 31;
    const int row0 = blockIdx.x * MT;
    if (tid < 128) { sb1[tid] = B1[tid]; sb2[tid] = B2[tid]; }
    stage_A(sAhi, sAlo, X, row0);

    float acc0[8][4], acc1[8][4];
    layer(sAhi, sAlo, sB, gwf + WI_WF1*4096, wid, lane, acc0, acc1);
    write_H(sAhi, sAlo, acc0, acc1, sb1, wid, lane);
    layer(sAhi, sAlo, sB, gwf + WI_WF2*4096, wid, lane, acc0, acc1);

    int g = lane >> 2, c = lane & 3;
    int r0 = row0 + wid*16 + g;
    #pragma unroll
    for (int half = 0; half < 2; half++) {
        float (*acc)[4] = half ? acc1 : acc0;
        #pragma unroll
        for (int nt = 0; nt < 8; nt++) {
            int col = half*64 + nt*8 + 2*c;
            float b0 = sb2[col], b1 = sb2[col+1];
            #pragma unroll
            for (int pr = 0; pr < 2; pr++) {
                int row = r0 + pr*8;
                if (row < NN) {
                    float2 xv = *(const float2*)(X + (size_t)row*128 + col);
                    float2 o;
                    o.x = xv.x + acc[nt][pr*2]   + b0;
                    o.y = xv.y + acc[nt][pr*2+1] + b1;
                    *(float2*)(OUT + (size_t)row*128 + col) = o;
                }
            }
        }
    }
}

// ================= gin_a: partial = t + mlp_a(ua) + b2a -> g_ua =================
__global__ __launch_bounds__(MMT, 2) void gin_a_mm(
    float* __restrict__ ua, const float* __restrict__ t,
    const uint4* __restrict__ gwf,
    const float* __restrict__ b1a, const float* __restrict__ b2a)
{
    extern __shared__ char smc[];
    u32* sAhi = (u32*)(smc + S_AHI);
    u32* sAlo = (u32*)(smc + S_ALO);
    u32* sB   = (u32*)(smc + S_B);
    float* s_b1a = (float*)(smc + S_BIAS);
    float* s_b2a = (float*)(smc + S_BIAS + 512);

    const int tid = threadIdx.x;
    const int wid = tid >> 5, lane = tid & 31;
    const int g = lane >> 2, c = lane & 3;
    const int row0 = blockIdx.x * MT;
    const int r0 = row0 + wid*16 + g;

    if (tid < 128) { s_b1a[tid] = b1a[tid]; s_b2a[tid] = b2a[tid]; }
    stage_A(sAhi, sAlo, ua, row0);

    float acc0[8][4], acc1[8][4];
    layer(sAhi, sAlo, sB, gwf + WI_W1A*4096, wid, lane, acc0, acc1);
    write_H(sAhi, sAlo, acc0, acc1, s_b1a, wid, lane);
    layer(sAhi, sAlo, sB, gwf + WI_W2A*4096, wid, lane, acc0, acc1);

    #pragma unroll
    for (int half = 0; half < 2; half++) {
        float (*acc)[4] = half ? acc1 : acc0;
        #pragma unroll
        for (int nt = 0; nt < 8; nt++) {
            int col = half*64 + nt*8 + 2*c;
            float b0 = s_b2a[col], b1 = s_b2a[col+1];
            #pragma unroll
            for (int pr = 0; pr < 2; pr++) {
                int row = r0 + pr*8;
                if (row < NN) {
                    float2 tv = *(const float2*)(t + (size_t)row*128 + col);
                    float2 o;
                    o.x = tv.x + acc[nt][pr*2]   + b0;
                    o.y = tv.y + acc[nt][pr*2+1] + b1;
                    *(float2*)(ua + (size_t)row*128 + col) = o;
                }
            }
        }
    }
}

// ================= fused_rest: gin_b + t2 + out-Linear + LN =================
__global__ __launch_bounds__(MMT, 2) void fused_rest_mm(
    const float* __restrict__ partial, const float* __restrict__ ub,
    const uint4* __restrict__ gwf,
    const float* __restrict__ b1b, const float* __restrict__ b2b,
    const float* __restrict__ bo,
    const float* __restrict__ lng, const float* __restrict__ lnb,
    float* __restrict__ OUT)
{
    extern __shared__ char smc[];
    u32* sAhi = (u32*)(smc + S_AHI);
    u32* sAlo = (u32*)(smc + S_ALO);
    u32* sB   = (u32*)(smc + S_B);
    float* s_b1b = (float*)(smc + S_BIAS);
    float* s_b2b = (float*)(smc + S_BIAS + 512);
    float* s_bo  = (float*)(smc + S_BIAS + 1024);
    float* s_g   = (float*)(smc + S_BIAS + 1536);
    float* s_be  = (float*)(smc + S_BIAS + 2048);

    const int tid = threadIdx.x;
    const int wid = tid >> 5, lane = tid & 31;
    const int g = lane >> 2, c = lane & 3;
    const int row0 = blockIdx.x * MT;
    const int r0 = row0 + wid*16 + g;

    if (tid < 128) {
        s_b1b[tid] = b1b[tid]; s_b2b[tid] = b2b[tid];
        s_bo[tid]  = bo[tid];  s_g[tid]   = lng[tid]; s_be[tid] = lnb[tid];
    }
    stage_A(sAhi, sAlo, ub, row0);

    float acc0[8][4], acc1[8][4];
    layer(sAhi, sAlo, sB, gwf + WI_W1B*4096, wid, lane, acc0, acc1);
    write_H(sAhi, sAlo, acc0, acc1, s_b1b, wid, lane);
    layer(sAhi, sAlo, sB, gwf + WI_W2B*4096, wid, lane, acc0, acc1);

    #pragma unroll
    for (int half = 0; half < 2; half++) {
        float (*acc)[4] = half ? acc1 : acc0;
        #pragma unroll
        for (int nt = 0; nt < 8; nt++) {
            int col = half*64 + nt*8 + 2*c;
            float b0 = s_b2b[col], b1 = s_b2b[col+1];
            int j = col >> 1;
            int ks = j >> 3;
            int ln = g*4 + (j & 3);
            int base = ((ks*8 + wid)*32 + ln)*4 + ((j & 4) ? 2 : 0);
            #pragma unroll
            for (int pr = 0; pr < 2; pr++) {
                int row = r0 + pr*8;
                float p0 = 0.f, p1 = 0.f;
                if (row < NN) {
                    float2 pv = *(const float2*)(partial + (size_t)row*128 + col);
                    p0 = pv.x; p1 = pv.y;
                }
                float v0 = fmaxf(p0 + acc[nt][pr*2]   + b0, 0.f);
                float v1 = fmaxf(p1 + acc[nt][pr*2+1] + b1, 0.f);
                u32 hp = pkbf(v0, v1);
                u32 lp = pkbf(v0 - bf_lo(hp), v1 - bf_hi(hp));
                sAhi[base + pr] = hp;
                sAlo[base + pr] = lp;
            }
        }
    }

    layer(sAhi, sAlo, sB, gwf + WI_WO*4096, wid, lane, acc0, acc1);

    float s0 = 0.f, q0 = 0.f, s1 = 0.f, q1 = 0.f;
    #pragma unroll
    for (int half = 0; half < 2; half++) {
        float (*acc)[4] = half ? acc1 : acc0;
        #pragma unroll
        for (int nt = 0; nt < 8; nt++) {
            int col = half*64 + nt*8 + 2*c;
            float b0 = s_bo[col], b1 = s_bo[col+1];
            float z00 = fmaxf(acc[nt][0] + b0, 0.f);
            float z01 = fmaxf(acc[nt][1] + b1, 0.f);
            float z10 = fmaxf(acc[nt][2] + b0, 0.f);
            float z11 = fmaxf(acc[nt][3] + b1, 0.f);
            s0 += z00 + z01; q0 += z00*z00 + z01*z01;
            s1 += z10 + z11; q1 += z10*z10 + z11*z11;
        }
    }
    #pragma unroll
    for (int d = 1; d <= 2; d <<= 1) {
        s0 += __shfl_xor_sync(0xffffffffu, s0, d);
        q0 += __shfl_xor_sync(0xffffffffu, q0, d);
        s1 += __shfl_xor_sync(0xffffffffu, s1, d);
        q1 += __shfl_xor_sync(0xffffffffu, q1, d);
    }
    float m0 = s0*(1.f/128.f), m1 = s1*(1.f/128.f);
    float rs0 = rsqrtf(q0*(1.f/128.f) - m0*m0 + 1e-5f);
    float rs1 = rsqrtf(q1*(1.f/128.f) - m1*m1 + 1e-5f);

    #pragma unroll
    for (int half = 0; half < 2; half++) {
        float (*acc)[4] = half ? acc1 : acc0;
        #pragma unroll
        for (int nt = 0; nt < 8; nt++) {
            int col = half*64 + nt*8 + 2*c;
            float b0 = s_bo[col], b1 = s_bo[col+1];
            float g0 = s_g[col], g1 = s_g[col+1];
            float e0 = s_be[col], e1 = s_be[col+1];
            int j = col >> 1;
            int ks = j >> 3;
            int ln = g*4 + (j & 3);
            int base = ((ks*8 + wid)*32 + ln)*4 + ((j & 4) ? 2 : 0);
            #pragma unroll
            for (int pr = 0; pr < 2; pr++) {
                int row = r0 + pr*8;
                if (row < NN) {
                    float mm = pr ? m1 : m0;
                    float rr = pr ? rs1 : rs0;
                    u32 hp = sAhi[base + pr], lp = sAlo[base + pr];
                    float t20 = bf_lo(hp) + bf_lo(lp);
                    float t21 = bf_hi(hp) + bf_hi(lp);
                    float z0 = fmaxf(acc[nt][pr*2]   + b0, 0.f);
                    float z1 = fmaxf(acc[nt][pr*2+1] + b1, 0.f);
                    float2 o;
                    o.x = t20 + (z0 - mm)*rr*g0 + e0;
                    o.y = t21 + (z1 - mm)*rr*g1 + e1;
                    *(float2*)(OUT + (size_t)row*128 + col) = o;
                }
            }
        }
    }
}

// ---------------- CSR construction ----------------
__global__ void hist_kernel(const int* __restrict__ et, const int* __restrict__ ex) {
    int i = blockIdx.x*blockDim.x + threadIdx.x;
    if (i < EE) {
        atomicAdd(&g_cnt[et[EE + i]], 1);
        atomicAdd(&g_cnt[NN + ex[EE + i]], 1);
    }
}

__global__ void scan1_kernel() {
    __shared__ int s[SCAN_B];
    int i = blockIdx.x*SCAN_B + threadIdx.x;
    int v = (i < TWO_N) ? g_cnt[i] : 0;
    s[threadIdx.x] = v;
    __syncthreads();
    #pragma unroll
    for (int d = 1; d < SCAN_B; d <<= 1) {
        int tv = (threadIdx.x >= d) ? s[threadIdx.x - d] : 0;
        __syncthreads();
        s[threadIdx.x] += tv;
        __syncthreads();
    }
    if (i < TWO_N) g_off[i + 1] = s[threadIdx.x];
    if (threadIdx.x == SCAN_B - 1) g_bsum[blockIdx.x] = s[SCAN_B - 1];
}

// merged scan2+scan3: each block serially prefixes the (<=196) raw block sums it needs
__global__ void scan3b_kernel() {
    __shared__ int s_pref[2];
    int B = blockIdx.x * blockDim.x;
    if (threadIdx.x == 0) {
        int i0 = (B == 0) ? 1 : B;                 // first i>=1 in this block
        int k0 = (i0 - 1) >> 9;                    // first bsum bucket used
        int p = 0;
        for (int j = 0; j < k0; j++) p += g_bsum[j];
        s_pref[0] = p;
        s_pref[1] = p + ((k0 < NSB) ? g_bsum[k0] : 0);
    }
    __syncthreads();
    int i = B + threadIdx.x;
    if (i == 0) { g_off[0] = 0; g_cnt[0] = 0; }
    else if (i <= TWO_N) {
        int i0 = (B == 0) ? 1 : B;
        int k0 = (i0 - 1) >> 9;
        int k  = (i - 1) >> 9;
        int pref = (k == k0) ? s_pref[0] : s_pref[1];
        int v = g_off[i] + pref;
        g_off[i] = v;
        if (i < TWO_N) g_cnt[i] = v;
    }
}

__global__ void fillA_kernel(const int* __restrict__ et) {
    int i = blockIdx.x*blockDim.x + threadIdx.x;
    if (i < EE) {
        int p = atomicAdd(&g_cnt[et[EE + i]], 1);
        g_col[p] = et[i];
    }
}

__global__ void fillB_kernel(const int* __restrict__ ex) {
    int i = blockIdx.x*blockDim.x + threadIdx.x;
    if (i < EE) {
        int q = atomicAdd(&g_cnt[NN + ex[EE + i]], 1);
        g_col[q] = ex[i];
    }
}

// agg set A: ua = t + sum t16[src]
__global__ void aggA_kernel(const float* __restrict__ t, float* __restrict__ ua) {
    int warp = (blockIdx.x*blockDim.x + threadIdx.x) >> 5;
    int lane = threadIdx.x & 31;
    if (warp >= NN) return;
    const float4* t4 = (const float4*)t;
    const uint2* s16 = (const uint2*)g_t16;
    float4 aA = t4[warp*32 + lane];
    int e = g_off[warp], eE = g_off[warp + 1];
    for (; e + 3 < eE; e += 4) {
        int s0 = g_col[e], s1 = g_col[e+1], s2 = g_col[e+2], s3 = g_col[e+3];
        uint2 v0 = s16[s0*32 + lane];
        uint2 v1 = s16[s1*32 + lane];
        uint2 v2 = s16[s2*32 + lane];
        uint2 v3 = s16[s3*32 + lane];
        float2 a0 = __half22float2(*(__half2*)&v0.x), b0 = __half22float2(*(__half2*)&v0.y);
        float2 a1 = __half22float2(*(__half2*)&v1.x), b1 = __half22float2(*(__half2*)&v1.y);
        float2 a2 = __half22float2(*(__half2*)&v2.x), b2 = __half22float2(*(__half2*)&v2.y);
        float2 a3 = __half22float2(*(__half2*)&v3.x), b3 = __half22float2(*(__half2*)&v3.y);
        aA.x += a0.x + a1.x + a2.x + a3.x;
        aA.y += a0.y + a1.y + a2.y + a3.y;
        aA.z += b0.x + b1.x + b2.x + b3.x;
        aA.w += b0.y + b1.y + b2.y + b3.y;
    }
    for (; e < eE; e++) {
        int s0 = g_col[e];
        uint2 v0 = s16[s0*32 + lane];
        float2 a0 = __half22float2(*(__half2*)&v0.x), b0 = __half22float2(*(__half2*)&v0.y);
        aA.x += a0.x; aA.y += a0.y; aA.z += b0.x; aA.w += b0.y;
    }
    ((float4*)ua)[warp*32 + lane] = aA;
}

// agg set B: ub = t + sum x16[src]
__global__ void aggB_kernel(const float* __restrict__ t, float* __restrict__ ub) {
    int warp = (blockIdx.x*blockDim.x + threadIdx.x) >> 5;
    int lane = threadIdx.x & 31;
    if (warp >= NN) return;
    const float4* t4 = (const float4*)t;
    const uint2* s16 = (const uint2*)g_x16;
    float4 aB = t4[warp*32 + lane];
    int e = g_off[NN + warp], eE = g_off[NN + warp + 1];
    for (; e + 3 < eE; e += 4) {
        int s0 = g_col[e], s1 = g_col[e+1], s2 = g_col[e+2], s3 = g_col[e+3];
        uint2 v0 = s16[s0*32 + lane];
        uint2 v1 = s16[s1*32 + lane];
        uint2 v2 = s16[s2*32 + lane];
        uint2 v3 = s16[s3*32 + lane];
        float2 a0 = __half22float2(*(__half2*)&v0.x), b0 = __half22float2(*(__half2*)&v0.y);
        float2 a1 = __half22float2(*(__half2*)&v1.x), b1 = __half22float2(*(__half2*)&v1.y);
        float2 a2 = __half22float2(*(__half2*)&v2.x), b2 = __half22float2(*(__half2*)&v2.y);
        float2 a3 = __half22float2(*(__half2*)&v3.x), b3 = __half22float2(*(__half2*)&v3.y);
        aB.x += a0.x + a1.x + a2.x + a3.x;
        aB.y += a0.y + a1.y + a2.y + a3.y;
        aB.z += b0.x + b1.x + b2.x + b3.x;
        aB.w += b0.y + b1.y + b2.y + b3.y;
    }
    for (; e < eE; e++) {
        int s0 = g_col[e];
        uint2 v0 = s16[s0*32 + lane];
        float2 a0 = __half22float2(*(__half2*)&v0.x), b0 = __half22float2(*(__half2*)&v0.y);
        aB.x += a0.x; aB.y += a0.y; aB.z += b0.x; aB.w += b0.y;
    }
    ((float4*)ub)[warp*32 + lane] = aB;
}

// ---------------- launcher ----------------
extern "C" void kernel_launch(void* const* d_in, const int* in_sizes, int n_in,
                              void* d_out, int out_size) {
    const float* x   = (const float*)d_in[0];
    const float* t   = (const float*)d_in[1];
    const int*   et  = (const int*)d_in[2];
    const int*   ex  = (const int*)d_in[3];
    const float* W1a = (const float*)d_in[4];
    const float* b1a = (const float*)d_in[5];
    const float* W2a = (const float*)d_in[6];
    const float* b2a = (const float*)d_in[7];
    const float* W1b = (const float*)d_in[8];
    const float* b1b = (const float*)d_in[9];
    const float* W2b = (const float*)d_in[10];
    const float* b2b = (const float*)d_in[11];
    const float* Wo  = (const float*)d_in[12];
    const float* bo  = (const float*)d_in[13];
    const float* lng = (const float*)d_in[14];
    const float* lnb = (const float*)d_in[15];
    const float* Wf1 = (const float*)d_in[16];
    const float* bf1 = (const float*)d_in[17];
    const float* Wf2 = (const float*)d_in[18];
    const float* bf2 = (const float*)d_in[19];
    float* out = (float*)d_out;

    float *pua, *pub;
    uint4* pwf;
    int* pcnt;
    cudaGetSymbolAddress((void**)&pua, g_ua);
    cudaGetSymbolAddress((void**)&pub, g_ub);
    cudaGetSymbolAddress((void**)&pwf, g_wfrag);
    cudaGetSymbolAddress((void**)&pcnt, g_cnt);

    cudaFuncSetAttribute(fc_x_mm,       cudaFuncAttributeMaxDynamicSharedMemorySize, SMEM_MM);
    cudaFuncSetAttribute(gin_a_mm,      cudaFuncAttributeMaxDynamicSharedMemorySize, SMEM_MM);
    cudaFuncSetAttribute(fused_rest_mm, cudaFuncAttributeMaxDynamicSharedMemorySize, SMEM_MM);

    cudaStream_t side;
    cudaStreamCreateWithFlags(&side, cudaStreamNonBlocking);
    cudaEvent_t eFork, eCv, eS3, eFB, eA, eG;
    cudaEventCreateWithFlags(&eFork, cudaEventDisableTiming);
    cudaEventCreateWithFlags(&eCv, cudaEventDisableTiming);
    cudaEventCreateWithFlags(&eS3, cudaEventDisableTiming);
    cudaEventCreateWithFlags(&eFB, cudaEventDisableTiming);
    cudaEventCreateWithFlags(&eA, cudaEventDisableTiming);
    cudaEventCreateWithFlags(&eG, cudaEventDisableTiming);

    cudaEventRecord(eFork, 0);
    cudaStreamWaitEvent(side, eFork, 0);

    // launch #1 (side): fp16 conversion
    conv16_kernel<<<(NN*64 + 255)/256, 256, 0, side>>>(t, x);
    cudaEventRecord(eCv, side);

    // main: CSR build (zero via memset node; scan chain compressed to 2 kernels)
    cudaMemsetAsync(pcnt, 0, TWO_N*sizeof(int), 0);
    hist_kernel<<<(EE + 255)/256, 256>>>(et, ex);                  // #2
    scan1_kernel<<<NSB, SCAN_B>>>();                               // #3
    scan3b_kernel<<<(TWO_N + 1 + 255)/256, 256>>>();               // #4
    cudaEventRecord(eS3, 0);
    fillA_kernel<<<(EE + 255)/256, 256>>>(et);                     // #5
    cudaStreamWaitEvent(0, eCv, 0);
    aggA_kernel<<<(NN + 7)/8, 256>>>(t, pua);                      // #6 <- profiled
    cudaEventRecord(eA, 0);

    // side: weight prep -> fc_x (concurrent with CSR/agg on main)
    prep_w<<<(7*4096 + 255)/256, 256, 0, side>>>(W1a, W2a, W1b, W2b, Wo, Wf1, Wf2);
    fc_x_mm<<<NBLK_MM, MMT, SMEM_MM, side>>>(x, pwf, bf1, bf2, out);

    // side: fillB after scan3b (overlaps fillA/aggA), then gin_a after aggA
    cudaStreamWaitEvent(side, eS3, 0);
    fillB_kernel<<<(EE + 255)/256, 256, 0, side>>>(ex);
    cudaEventRecord(eFB, side);
    cudaStreamWaitEvent(side, eA, 0);
    gin_a_mm<<<NBLK_MM, MMT, SMEM_MM, side>>>(pua, t, pwf, b1a, b2a);
    cudaEventRecord(eG, side);

    // main: aggB, then join for fused_rest
    cudaStreamWaitEvent(0, eFB, 0);
    aggB_kernel<<<(NN + 7)/8, 256>>>(t, pub);
    cudaStreamWaitEvent(0, eG, 0);
    fused_rest_mm<<<NBLK_MM, MMT, SMEM_MM>>>(pua, pub, pwf,
        b1b, b2b, bo, lng, lnb, out + (size_t)NN*DD);

    cudaEventDestroy(eFork);
    cudaEventDestroy(eCv);
    cudaEventDestroy(eS3);
    cudaEventDestroy(eFB);
    cudaEventDestroy(eA);
    cudaEventDestroy(eG);
    cudaStreamDestroy(side);
}